// round 7
// baseline (speedup 1.0000x reference)
#include <cuda_runtime.h>
#include <cstdint>

#define Bb 8
#define Nn_ 1024
#define Dd 1024
#define Hh 16
#define HD 64
#define QSCALE 0.125f   // 64^-0.5, exact power of two

// ---- device-global scratch (tf32 bit patterns stored as uint32) ----
__device__ uint32_t g_x32[Bb * Nn_ * Dd];        // x, tf32
__device__ uint32_t g_wq32[Dd * 3 * Dd];         // W_qkv, tf32
__device__ uint32_t g_wo32[Dd * Dd];             // W_o, tf32
__device__ uint32_t g_q32[Bb * Hh * Nn_ * HD];   // Q, tf32, pre-scaled
__device__ uint32_t g_khi[Bb * Hh * Nn_ * HD];   // split K
__device__ uint32_t g_klo[Bb * Hh * Nn_ * HD];
__device__ uint32_t g_vhi[Bb * Hh * Nn_ * HD];   // split V
__device__ uint32_t g_vlo[Bb * Hh * Nn_ * HD];
__device__ uint32_t g_heads32[Bb * Nn_ * Dd];    // attention out, tf32

// ---------------------------------------------------------------------------
// helpers
// ---------------------------------------------------------------------------
__device__ __forceinline__ uint32_t f2tf32(float f) {
    uint32_t u;
    asm("cvt.rna.tf32.f32 %0, %1;" : "=r"(u) : "f"(f));
    return u;
}

__device__ __forceinline__ void mma_tf32(float c[4],
                                         uint32_t a0, uint32_t a1,
                                         uint32_t a2, uint32_t a3,
                                         uint32_t b0, uint32_t b1) {
    asm volatile(
        "mma.sync.aligned.m16n8k8.row.col.f32.tf32.tf32.f32 "
        "{%0,%1,%2,%3}, {%4,%5,%6,%7}, {%8,%9}, {%0,%1,%2,%3};"
        : "+f"(c[0]), "+f"(c[1]), "+f"(c[2]), "+f"(c[3])
        : "r"(a0), "r"(a1), "r"(a2), "r"(a3), "r"(b0), "r"(b1));
}

__device__ __forceinline__ void cp16(void* dst, const void* src) {
    uint32_t d = (uint32_t)__cvta_generic_to_shared(dst);
    asm volatile("cp.async.cg.shared.global [%0], [%1], 16;" :: "r"(d), "l"(src));
}
__device__ __forceinline__ void cp_commit() {
    asm volatile("cp.async.commit_group;");
}
template <int N_>
__device__ __forceinline__ void cp_wait() {
    asm volatile("cp.async.wait_group %0;" :: "n"(N_));
}

// ---------------------------------------------------------------------------
// One-time tf32 conversion of inputs (dst selected IN DEVICE CODE).
// which: 0 -> g_x32, 1 -> g_wq32, 2 -> g_wo32
// ---------------------------------------------------------------------------
__global__ __launch_bounds__(256)
void cvt_kernel(const float4* __restrict__ in, int n4, int which)
{
    uint32_t* dst = (which == 0) ? g_x32 : (which == 1) ? g_wq32 : g_wo32;
    int i = blockIdx.x * blockDim.x + threadIdx.x;
    if (i < n4) {
        float4 v = in[i];
        ((uint4*)dst)[i] = make_uint4(f2tf32(v.x), f2tf32(v.y),
                                      f2tf32(v.z), f2tf32(v.w));
    }
}

// ---------------------------------------------------------------------------
// TF32 tensor-core GEMM, cp.async double-buffered.
// Block 128x128, BK=32, 256 threads = 8 warps (2M x 4N), warp tile 64x32.
// A/W are pre-converted tf32 device globals, bound IN DEVICE CODE.
// MODE 1: A=g_x32, W=g_wq32 (K=1024,N=3072), QKV scatter epilogue
//         (Q scaled tf32 -> g_q32; K,V split -> g_khi/lo, g_vhi/lo)
// MODE 2: A=g_heads32, W=g_wo32 (K=1024,N=1024), fp32 C + bias
// Dynamic smem: As[2][128][36] + Bs[2][32][136] = 71,680 B.
// Stride 36 -> A-frag banks 4*lr+lc (conflict-free); 136 -> 8*lc+lr (cf).
// ---------------------------------------------------------------------------
template <int MODE>
__global__ __launch_bounds__(256)
void gemm_tc(const float* __restrict__ bias, float* __restrict__ C,
             int M, int N, int K)
{
    extern __shared__ uint32_t sgm[];
    uint32_t* As = sgm;                  // [2][128][36]
    uint32_t* Bs = sgm + 2 * 128 * 36;   // [2][32][136]

    const uint32_t* __restrict__ A = (MODE == 1) ? g_x32  : g_heads32;
    const uint32_t* __restrict__ W = (MODE == 1) ? g_wq32 : g_wo32;

    const int tid  = threadIdx.x;
    const int lane = tid & 31;
    const int warp = tid >> 5;
    const int warpM = warp & 1;
    const int warpN = warp >> 1;
    const int lr = lane >> 2;
    const int lc = lane & 3;

    const int r0 = blockIdx.y * 128;
    const int c0 = blockIdx.x * 128;

    // async-copy mapping: A row=tid/2, 16 words each; B k=tid/8, 16 words each
    const int a_row = tid >> 1, a_k = (tid & 1) * 16;
    const int b_k   = tid >> 3, b_c = (tid & 7) * 16;

    const uint32_t* agp = A + (size_t)(r0 + a_row) * K + a_k;
    const uint32_t* bgp = W + (size_t)b_k * N + c0 + b_c;
    uint32_t* adp = As + a_row * 36 + a_k;
    uint32_t* bdp = Bs + b_k * 136 + b_c;

#define LOAD_STAGE(s, k0) do {                                              \
        uint32_t* ad = adp + (s) * (128 * 36);                              \
        const uint32_t* ag = agp + (k0);                                    \
        cp16(ad, ag); cp16(ad + 4, ag + 4);                                 \
        cp16(ad + 8, ag + 8); cp16(ad + 12, ag + 12);                       \
        uint32_t* bd = bdp + (s) * (32 * 136);                              \
        const uint32_t* bg = bgp + (size_t)(k0) * N;                        \
        cp16(bd, bg); cp16(bd + 4, bg + 4);                                 \
        cp16(bd + 8, bg + 8); cp16(bd + 12, bg + 12);                       \
        cp_commit();                                                        \
    } while (0)

    float acc[4][4][4];
#pragma unroll
    for (int i = 0; i < 4; i++)
#pragma unroll
        for (int j = 0; j < 4; j++)
#pragma unroll
            for (int r = 0; r < 4; r++) acc[i][j][r] = 0.0f;

    LOAD_STAGE(0, 0);

    int s = 0;
    for (int k0 = 0; k0 < K; k0 += 32) {
        if (k0 + 32 < K) { LOAD_STAGE(s ^ 1, k0 + 32); cp_wait<1>(); }
        else             { cp_wait<0>(); }
        __syncthreads();

        const uint32_t* Ax = As + s * (128 * 36);
        const uint32_t* Bx = Bs + s * (32 * 136);

#pragma unroll
        for (int kk = 0; kk < 32; kk += 8) {
            uint32_t af[4][4];
#pragma unroll
            for (int am = 0; am < 4; am++) {
                const int row = warpM * 64 + am * 16 + lr;
                af[am][0] = Ax[row * 36 + kk + lc];
                af[am][1] = Ax[(row + 8) * 36 + kk + lc];
                af[am][2] = Ax[row * 36 + kk + lc + 4];
                af[am][3] = Ax[(row + 8) * 36 + kk + lc + 4];
            }
            uint32_t bf[4][2];
#pragma unroll
            for (int bn = 0; bn < 4; bn++) {
                const int col = warpN * 32 + bn * 8 + lr;
                bf[bn][0] = Bx[(kk + lc) * 136 + col];
                bf[bn][1] = Bx[(kk + lc + 4) * 136 + col];
            }
#pragma unroll
            for (int am = 0; am < 4; am++)
#pragma unroll
                for (int bn = 0; bn < 4; bn++)
                    mma_tf32(acc[am][bn], af[am][0], af[am][1], af[am][2],
                             af[am][3], bf[bn][0], bf[bn][1]);
        }
        __syncthreads();
        s ^= 1;
    }
#undef LOAD_STAGE

    // ---- epilogue ----
#pragma unroll
    for (int am = 0; am < 4; am++) {
        const int row0 = r0 + warpM * 64 + am * 16 + lr;
        const int row1 = row0 + 8;
#pragma unroll
        for (int bn = 0; bn < 4; bn++) {
            const int atomcol = c0 + warpN * 32 + bn * 8;
            const int colp = atomcol + lc * 2;
            const float b0v = bias[colp];
            const float b1v = bias[colp + 1];
            float v00 = acc[am][bn][0] + b0v, v01 = acc[am][bn][1] + b1v;
            float v10 = acc[am][bn][2] + b0v, v11 = acc[am][bn][3] + b1v;

            if (MODE == 2) {
                *(float2*)(C + (size_t)row0 * N + colp) = make_float2(v00, v01);
                *(float2*)(C + (size_t)row1 * N + colp) = make_float2(v10, v11);
            } else {
                // col -> (h, t, d): 8-col atom never crosses a 64/192 boundary
                const int h     = atomcol / 192;
                const int rem   = atomcol % 192;
                const int t     = rem / 64;          // 0=q 1=k 2=v
                const int dbase = (rem % 64) + lc * 2;
                const int b0r = row0 >> 10, n0 = row0 & 1023;
                const int b1r = row1 >> 10, n1 = row1 & 1023;
                const size_t off0 = (((size_t)(b0r * Hh + h) << 10) + n0) * HD + dbase;
                const size_t off1 = (((size_t)(b1r * Hh + h) << 10) + n1) * HD + dbase;

                if (t == 0) {
                    *(uint2*)(g_q32 + off0) = make_uint2(f2tf32(v00 * QSCALE),
                                                         f2tf32(v01 * QSCALE));
                    *(uint2*)(g_q32 + off1) = make_uint2(f2tf32(v10 * QSCALE),
                                                         f2tf32(v11 * QSCALE));
                } else {
                    uint32_t* dhi = (t == 1) ? g_khi : g_vhi;
                    uint32_t* dlo = (t == 1) ? g_klo : g_vlo;
                    uint32_t h00 = f2tf32(v00), h01 = f2tf32(v01);
                    uint32_t h10 = f2tf32(v10), h11 = f2tf32(v11);
                    *(uint2*)(dhi + off0) = make_uint2(h00, h01);
                    *(uint2*)(dhi + off1) = make_uint2(h10, h11);
                    *(uint2*)(dlo + off0) =
                        make_uint2(f2tf32(v00 - __uint_as_float(h00)),
                                   f2tf32(v01 - __uint_as_float(h01)));
                    *(uint2*)(dlo + off1) =
                        make_uint2(f2tf32(v10 - __uint_as_float(h10)),
                                   f2tf32(v11 - __uint_as_float(h11)));
                }
            }
        }
    }
}

// ---------------------------------------------------------------------------
// Tensor-core flash attention: operands pre-converted/pre-split in globals.
// Block = (bh, 64 q-rows), 128 threads = 4 warps, K/V tiles of 32.
// Dynamic smem 65,536 B (same layout/strides as R6 -- all conflict-free).
// ---------------------------------------------------------------------------
#define ATTN_SMEM_BYTES 65536

__global__ __launch_bounds__(128)
void attn_mma_kernel()
{
    extern __shared__ uint32_t sm[];
    uint32_t* Qs  = sm;                       // 64*68
    uint32_t* Khi = sm + 4352;                // 64*40
    uint32_t* Klo = Khi + 2560;
    uint32_t* Vhi = Klo + 2560;               // 32*72
    uint32_t* Vlo = Vhi + 2304;
    uint32_t* Ps  = Vlo + 2304;               // 64*36

    const int tid  = threadIdx.x;
    const int lane = tid & 31;
    const int warp = tid >> 5;
    const int lr   = lane >> 2;
    const int lc   = lane & 3;

    const int bh = blockIdx.y;
    const int r0 = blockIdx.x * 64;
    const int b  = bh >> 4;
    const int h  = bh & 15;

    const uint32_t* qg  = g_q32 + (size_t)bh * Nn_ * HD;
    const uint32_t* khg = g_khi + (size_t)bh * Nn_ * HD;
    const uint32_t* klg = g_klo + (size_t)bh * Nn_ * HD;
    const uint32_t* vhg = g_vhi + (size_t)bh * Nn_ * HD;
    const uint32_t* vlg = g_vlo + (size_t)bh * Nn_ * HD;

    // ---- load Q tile (already tf32 + scaled): straight uint4 copies ----
#pragma unroll
    for (int i = 0; i < 8; i++) {
        int idx4 = i * 128 + tid;           // 0..1023
        int row  = idx4 >> 4;
        int d0   = (idx4 & 15) * 4;
        *(uint4*)&Qs[row * 68 + d0] =
            *(const uint4*)(qg + (size_t)(r0 + row) * HD + d0);
    }

    float oacc[8][4];
#pragma unroll
    for (int bn = 0; bn < 8; bn++)
#pragma unroll
        for (int r = 0; r < 4; r++) oacc[bn][r] = 0.0f;
    float m0 = -3.0e38f, m1 = -3.0e38f, l0 = 0.0f, l1 = 0.0f;

    const int wrow = warp * 16;

    __syncthreads();

    for (int kt = 0; kt < Nn_ / 32; kt++) {
        const int c0 = kt * 32;

        // ---- K tiles transposed (no cvt: already split tf32) ----
#pragma unroll
        for (int i = 0; i < 4; i++) {
            int idx4 = i * 128 + tid;
            int row  = idx4 & 31;
            int d0   = (idx4 >> 5) * 4;
            uint4 kh = *(const uint4*)(khg + (size_t)(c0 + row) * HD + d0);
            uint4 kl = *(const uint4*)(klg + (size_t)(c0 + row) * HD + d0);
            Khi[(d0 + 0) * 40 + row] = kh.x;
            Khi[(d0 + 1) * 40 + row] = kh.y;
            Khi[(d0 + 2) * 40 + row] = kh.z;
            Khi[(d0 + 3) * 40 + row] = kh.w;
            Klo[(d0 + 0) * 40 + row] = kl.x;
            Klo[(d0 + 1) * 40 + row] = kl.y;
            Klo[(d0 + 2) * 40 + row] = kl.z;
            Klo[(d0 + 3) * 40 + row] = kl.w;
        }
        // ---- V tiles natural: straight uint4 copies ----
#pragma unroll
        for (int i = 0; i < 4; i++) {
            int idx4 = i * 128 + tid;
            int row  = idx4 >> 4;
            int d0   = (idx4 & 15) * 4;
            *(uint4*)&Vhi[row * 72 + d0] =
                *(const uint4*)(vhg + (size_t)(c0 + row) * HD + d0);
            *(uint4*)&Vlo[row * 72 + d0] =
                *(const uint4*)(vlg + (size_t)(c0 + row) * HD + d0);
        }
        __syncthreads();

        // ---- S = Q @ K^T (2-term split on K) ----
        float sacc[4][4];
#pragma unroll
        for (int bn = 0; bn < 4; bn++)
#pragma unroll
            for (int r = 0; r < 4; r++) sacc[bn][r] = 0.0f;

#pragma unroll
        for (int kk = 0; kk < 64; kk += 8) {
            uint32_t a0 = Qs[(wrow + lr) * 68 + kk + lc];
            uint32_t a1 = Qs[(wrow + 8 + lr) * 68 + kk + lc];
            uint32_t a2 = Qs[(wrow + lr) * 68 + kk + lc + 4];
            uint32_t a3 = Qs[(wrow + 8 + lr) * 68 + kk + lc + 4];
#pragma unroll
            for (int bn = 0; bn < 4; bn++) {
                const int col = bn * 8 + lr;
                mma_tf32(sacc[bn], a0, a1, a2, a3,
                         Khi[(kk + lc) * 40 + col], Khi[(kk + lc + 4) * 40 + col]);
                mma_tf32(sacc[bn], a0, a1, a2, a3,
                         Klo[(kk + lc) * 40 + col], Klo[(kk + lc + 4) * 40 + col]);
            }
        }

        // ---- online softmax ----
        float rmax0 = -3.0e38f, rmax1 = -3.0e38f;
#pragma unroll
        for (int bn = 0; bn < 4; bn++) {
            rmax0 = fmaxf(rmax0, fmaxf(sacc[bn][0], sacc[bn][1]));
            rmax1 = fmaxf(rmax1, fmaxf(sacc[bn][2], sacc[bn][3]));
        }
        rmax0 = fmaxf(rmax0, __shfl_xor_sync(0xffffffffu, rmax0, 1));
        rmax0 = fmaxf(rmax0, __shfl_xor_sync(0xffffffffu, rmax0, 2));
        rmax1 = fmaxf(rmax1, __shfl_xor_sync(0xffffffffu, rmax1, 1));
        rmax1 = fmaxf(rmax1, __shfl_xor_sync(0xffffffffu, rmax1, 2));

        const float newm0 = fmaxf(m0, rmax0);
        const float newm1 = fmaxf(m1, rmax1);
        const float fac0  = __expf(m0 - newm0);
        const float fac1  = __expf(m1 - newm1);

        float p[4][4];
        float rsum0 = 0.0f, rsum1 = 0.0f;
#pragma unroll
        for (int bn = 0; bn < 4; bn++) {
            p[bn][0] = __expf(sacc[bn][0] - newm0);
            p[bn][1] = __expf(sacc[bn][1] - newm0);
            p[bn][2] = __expf(sacc[bn][2] - newm1);
            p[bn][3] = __expf(sacc[bn][3] - newm1);
            rsum0 += p[bn][0] + p[bn][1];
            rsum1 += p[bn][2] + p[bn][3];
        }
        rsum0 += __shfl_xor_sync(0xffffffffu, rsum0, 1);
        rsum0 += __shfl_xor_sync(0xffffffffu, rsum0, 2);
        rsum1 += __shfl_xor_sync(0xffffffffu, rsum1, 1);
        rsum1 += __shfl_xor_sync(0xffffffffu, rsum1, 2);

        l0 = l0 * fac0 + rsum0;  m0 = newm0;
        l1 = l1 * fac1 + rsum1;  m1 = newm1;
#pragma unroll
        for (int bn = 0; bn < 8; bn++) {
            oacc[bn][0] *= fac0; oacc[bn][1] *= fac0;
            oacc[bn][2] *= fac1; oacc[bn][3] *= fac1;
        }

        // ---- store P (tf32) to per-warp-private rows ----
#pragma unroll
        for (int bn = 0; bn < 4; bn++) {
            Ps[(wrow + lr) * 36 + bn * 8 + 2 * lc]         = f2tf32(p[bn][0]);
            Ps[(wrow + lr) * 36 + bn * 8 + 2 * lc + 1]     = f2tf32(p[bn][1]);
            Ps[(wrow + 8 + lr) * 36 + bn * 8 + 2 * lc]     = f2tf32(p[bn][2]);
            Ps[(wrow + 8 + lr) * 36 + bn * 8 + 2 * lc + 1] = f2tf32(p[bn][3]);
        }
        __syncwarp();

        // ---- O += P @ V (2-term split on V) ----
#pragma unroll
        for (int kk = 0; kk < 32; kk += 8) {
            uint32_t a0 = Ps[(wrow + lr) * 36 + kk + lc];
            uint32_t a1 = Ps[(wrow + 8 + lr) * 36 + kk + lc];
            uint32_t a2 = Ps[(wrow + lr) * 36 + kk + lc + 4];
            uint32_t a3 = Ps[(wrow + 8 + lr) * 36 + kk + lc + 4];
#pragma unroll
            for (int bn = 0; bn < 8; bn++) {
                const int col = bn * 8 + lr;
                mma_tf32(oacc[bn], a0, a1, a2, a3,
                         Vhi[(kk + lc) * 72 + col], Vhi[(kk + lc + 4) * 72 + col]);
                mma_tf32(oacc[bn], a0, a1, a2, a3,
                         Vlo[(kk + lc) * 72 + col], Vlo[(kk + lc + 4) * 72 + col]);
            }
        }
        __syncthreads();
    }

    // ---- finalize: heads tf32 -> g_heads32 ----
    const float inv0 = 1.0f / l0;
    const float inv1 = 1.0f / l1;
    const int row0 = r0 + wrow + lr;
    const int row1 = row0 + 8;
#pragma unroll
    for (int bn = 0; bn < 8; bn++) {
        const int col = h * HD + bn * 8 + 2 * lc;
        *(uint2*)(g_heads32 + ((size_t)(b * Nn_ + row0) * Dd) + col) =
            make_uint2(f2tf32(oacc[bn][0] * inv0), f2tf32(oacc[bn][1] * inv0));
        *(uint2*)(g_heads32 + ((size_t)(b * Nn_ + row1) * Dd) + col) =
            make_uint2(f2tf32(oacc[bn][2] * inv1), f2tf32(oacc[bn][3] * inv1));
    }
}

// ---------------------------------------------------------------------------
extern "C" void kernel_launch(void* const* d_in, const int* in_sizes, int n_in,
                              void* d_out, int out_size)
{
    // Resolve inputs BY SIZE (all element counts are distinct):
    const float *x = 0, *W_qkv = 0, *b_qkv = 0, *W_o = 0, *b_o = 0;
    for (int i = 0; i < n_in; i++) {
        const float* p = (const float*)d_in[i];
        switch (in_sizes[i]) {
            case 8388608: x     = p; break;
            case 3145728: W_qkv = p; break;
            case 3072:    b_qkv = p; break;
            case 1048576: W_o   = p; break;
            case 1024:    b_o   = p; break;
            default: break;
        }
    }
    float* out = (float*)d_out;

    const int M = Bb * Nn_;                          // 8192
    const int GEMM_SMEM = (2 * 128 * 36 + 2 * 32 * 136) * 4;   // 71,680 B

    cudaFuncSetAttribute(gemm_tc<1>,
                         cudaFuncAttributeMaxDynamicSharedMemorySize, GEMM_SMEM);
    cudaFuncSetAttribute(gemm_tc<2>,
                         cudaFuncAttributeMaxDynamicSharedMemorySize, GEMM_SMEM);
    cudaFuncSetAttribute(attn_mma_kernel,
                         cudaFuncAttributeMaxDynamicSharedMemorySize,
                         ATTN_SMEM_BYTES);

    // 0) one-time tf32 conversion of x, W_qkv, W_o
    cvt_kernel<<<8388608 / 4 / 256, 256>>>((const float4*)x,     8388608 / 4, 0);
    cvt_kernel<<<3145728 / 4 / 256, 256>>>((const float4*)W_qkv, 3145728 / 4, 1);
    cvt_kernel<<<1048576 / 4 / 256, 256>>>((const float4*)W_o,   1048576 / 4, 2);

    // 1) QKV projection (async-pipelined tf32 mma) + scatter/split epilogue
    {
        dim3 grid(3 * Dd / 128, M / 128);   // (24, 64)
        gemm_tc<1><<<grid, 256, GEMM_SMEM>>>(b_qkv, (float*)0, M, 3 * Dd, Dd);
    }

    // 2) Attention (tf32 mma flash, pre-split K/V)
    {
        dim3 grid(Nn_ / 64, Bb * Hh);       // (16, 128)
        attn_mma_kernel<<<grid, 128, ATTN_SMEM_BYTES>>>();
    }

    // 3) Output projection
    {
        dim3 grid(Dd / 128, M / 128);       // (8, 64)
        gemm_tc<2><<<grid, 256, GEMM_SMEM>>>(b_o, out, M, Dd, Dd);
    }
}

// round 8
// speedup vs baseline: 1.3596x; 1.3596x over previous
#include <cuda_runtime.h>
#include <cstdint>

#define Bb 8
#define Nn_ 1024
#define Dd 1024
#define Hh 16
#define HD 64
#define QSCALE 0.125f   // 64^-0.5, exact power of two

// Scratch (device globals: no allocations allowed)
__device__ uint32_t g_q32[Bb * Hh * Nn_ * HD];   // Q, tf32 bits, pre-scaled
__device__ uint32_t g_k32[Bb * Hh * Nn_ * HD];   // K, tf32 bits
__device__ uint32_t g_v32[Bb * Hh * Nn_ * HD];   // V, tf32 bits
__device__ float    g_heads[Bb * Nn_ * Dd];      // [b][n][h*HD+d]

// ---------------------------------------------------------------------------
// TF32 helpers
// ---------------------------------------------------------------------------
__device__ __forceinline__ uint32_t f2tf32(float f) {
    uint32_t u;
    asm("cvt.rna.tf32.f32 %0, %1;" : "=r"(u) : "f"(f));
    return u;
}

__device__ __forceinline__ void mma_tf32(float c[4],
                                         uint32_t a0, uint32_t a1,
                                         uint32_t a2, uint32_t a3,
                                         uint32_t b0, uint32_t b1) {
    asm volatile(
        "mma.sync.aligned.m16n8k8.row.col.f32.tf32.tf32.f32 "
        "{%0,%1,%2,%3}, {%4,%5,%6,%7}, {%8,%9}, {%0,%1,%2,%3};"
        : "+f"(c[0]), "+f"(c[1]), "+f"(c[2]), "+f"(c[3])
        : "r"(a0), "r"(a1), "r"(a2), "r"(a3), "r"(b0), "r"(b1));
}

// ---------------------------------------------------------------------------
// TF32 tensor-core GEMM (identical compute structure to R6 -- known 450us).
// Block 128x128, BK=16, 256 threads = 8 warps (2M x 4N), warp tile 64x32.
// MODE 1: QKV scatter epilogue -> g_q32/g_k32/g_v32 as tf32 bits (q scaled)
// MODE 2: A = g_heads (device bind), fp32 C + bias
// ---------------------------------------------------------------------------
template <int MODE>
__global__ __launch_bounds__(256)
void sgemm_kernel(const float* __restrict__ A,
                  const float* __restrict__ W,
                  const float* __restrict__ bias,
                  float* __restrict__ C,
                  int M, int N, int K)
{
    __shared__ uint32_t As[128][20];
    __shared__ uint32_t Bs[16][136];

    const float* __restrict__ Ain = (MODE == 2) ? (const float*)g_heads : A;

    const int tid  = threadIdx.x;
    const int lane = tid & 31;
    const int warp = tid >> 5;
    const int warpM = warp & 1;
    const int warpN = warp >> 1;

    const int r0 = blockIdx.y * 128;
    const int c0 = blockIdx.x * 128;

    const int a_row = tid >> 1;
    const int a_kc  = (tid & 1) * 8;
    const int b_kr  = tid >> 5;
    const int b_c4  = (tid & 31) * 4;

    const float* Aptr = Ain + (size_t)(r0 + a_row) * K + a_kc;

    float acc[4][4][4];
#pragma unroll
    for (int i = 0; i < 4; i++)
#pragma unroll
        for (int j = 0; j < 4; j++)
#pragma unroll
            for (int r = 0; r < 4; r++) acc[i][j][r] = 0.0f;

    const int lr = lane >> 2;
    const int lc = lane & 3;

    for (int k0 = 0; k0 < K; k0 += 16) {
        {
            float4 v0 = *(const float4*)(Aptr + k0);
            float4 v1 = *(const float4*)(Aptr + k0 + 4);
            As[a_row][a_kc + 0] = f2tf32(v0.x);
            As[a_row][a_kc + 1] = f2tf32(v0.y);
            As[a_row][a_kc + 2] = f2tf32(v0.z);
            As[a_row][a_kc + 3] = f2tf32(v0.w);
            As[a_row][a_kc + 4] = f2tf32(v1.x);
            As[a_row][a_kc + 5] = f2tf32(v1.y);
            As[a_row][a_kc + 6] = f2tf32(v1.z);
            As[a_row][a_kc + 7] = f2tf32(v1.w);
        }
#pragma unroll
        for (int i = 0; i < 2; i++) {
            int kr = b_kr + i * 8;
            float4 v = *(const float4*)(W + (size_t)(k0 + kr) * N + c0 + b_c4);
            Bs[kr][b_c4 + 0] = f2tf32(v.x);
            Bs[kr][b_c4 + 1] = f2tf32(v.y);
            Bs[kr][b_c4 + 2] = f2tf32(v.z);
            Bs[kr][b_c4 + 3] = f2tf32(v.w);
        }
        __syncthreads();

#pragma unroll
        for (int kk = 0; kk < 16; kk += 8) {
            uint32_t af[4][4];
#pragma unroll
            for (int am = 0; am < 4; am++) {
                const int row = warpM * 64 + am * 16 + lr;
                af[am][0] = As[row][kk + lc];
                af[am][1] = As[row + 8][kk + lc];
                af[am][2] = As[row][kk + lc + 4];
                af[am][3] = As[row + 8][kk + lc + 4];
            }
            uint32_t bf[4][2];
#pragma unroll
            for (int bn = 0; bn < 4; bn++) {
                const int col = warpN * 32 + bn * 8 + lr;
                bf[bn][0] = Bs[kk + lc][col];
                bf[bn][1] = Bs[kk + lc + 4][col];
            }
#pragma unroll
            for (int am = 0; am < 4; am++)
#pragma unroll
                for (int bn = 0; bn < 4; bn++)
                    mma_tf32(acc[am][bn], af[am][0], af[am][1], af[am][2], af[am][3],
                             bf[bn][0], bf[bn][1]);
        }
        __syncthreads();
    }

#pragma unroll
    for (int am = 0; am < 4; am++) {
        const int row0 = r0 + warpM * 64 + am * 16 + lr;
        const int row1 = row0 + 8;
#pragma unroll
        for (int bn = 0; bn < 4; bn++) {
            const int atomcol = c0 + warpN * 32 + bn * 8;
            const int colp = atomcol + lc * 2;
            const float b0v = bias[colp];
            const float b1v = bias[colp + 1];
            float v00 = acc[am][bn][0] + b0v, v01 = acc[am][bn][1] + b1v;
            float v10 = acc[am][bn][2] + b0v, v11 = acc[am][bn][3] + b1v;

            if (MODE == 2) {
                *(float2*)(C + (size_t)row0 * N + colp) = make_float2(v00, v01);
                *(float2*)(C + (size_t)row1 * N + colp) = make_float2(v10, v11);
            } else {
                // col -> (h, t, d): 8-col atom never crosses a 64/192 boundary
                const int h     = atomcol / 192;
                const int rem   = atomcol % 192;
                const int t     = rem / 64;          // 0=q 1=k 2=v
                const int dbase = (rem % 64) + lc * 2;
                uint32_t* dst = (t == 0) ? g_q32 : (t == 1) ? g_k32 : g_v32;
                const float sc = (t == 0) ? QSCALE : 1.0f;

                const int b0r = row0 >> 10, n0 = row0 & 1023;
                const int b1r = row1 >> 10, n1 = row1 & 1023;
                const size_t off0 = (((size_t)(b0r * Hh + h) << 10) + n0) * HD + dbase;
                const size_t off1 = (((size_t)(b1r * Hh + h) << 10) + n1) * HD + dbase;
                *(uint2*)(dst + off0) = make_uint2(f2tf32(v00 * sc), f2tf32(v01 * sc));
                *(uint2*)(dst + off1) = make_uint2(f2tf32(v10 * sc), f2tf32(v11 * sc));
            }
        }
    }
}

// ---------------------------------------------------------------------------
// Tensor-core flash attention, single-tf32 (no splits), STATIC smem 46,080 B.
// Block = (bh, 64 q-rows), 128 threads = 4 warps (warp w: rows 16w..16w+15),
// K/V tiles of 32. Operands are pre-converted tf32 bits (zero cvt in loop).
//   Qs[64][68] [row][d]   A-frag LDS conflict-free (68%32=4 -> 4lr+lc)
//   Ks[64][40] [d][seq]   B-frag conflict-free (40%32=8 -> 8lc+lr)
//   Vs[32][72] [seq][d]   B-frag conflict-free (72%32=8)
//   Ps[64][36] [row][seq] A-frag conflict-free (36%32=4)
// 4 blocks/SM (vs 3 in R6), half the HMMA count of R6.
// ---------------------------------------------------------------------------
__global__ __launch_bounds__(128, 4)
void attn_mma_kernel()
{
    __shared__ uint32_t Qs[64][68];
    __shared__ uint32_t Ks[64][40];
    __shared__ uint32_t Vs[32][72];
    __shared__ uint32_t Ps[64][36];

    const int tid  = threadIdx.x;
    const int lane = tid & 31;
    const int warp = tid >> 5;
    const int lr   = lane >> 2;
    const int lc   = lane & 3;

    const int bh = blockIdx.y;
    const int r0 = blockIdx.x * 64;
    const int b  = bh >> 4;
    const int h  = bh & 15;

    const uint32_t* qg = g_q32 + (size_t)bh * Nn_ * HD;
    const uint32_t* kg = g_k32 + (size_t)bh * Nn_ * HD;
    const uint32_t* vg = g_v32 + (size_t)bh * Nn_ * HD;

    // ---- Q tile: straight uint4 copies ----
#pragma unroll
    for (int i = 0; i < 8; i++) {
        int idx4 = i * 128 + tid;           // 0..1023
        int row  = idx4 >> 4;
        int d0   = (idx4 & 15) * 4;
        *(uint4*)&Qs[row][d0] = *(const uint4*)(qg + (size_t)(r0 + row) * HD + d0);
    }

    float oacc[8][4];
#pragma unroll
    for (int bn = 0; bn < 8; bn++)
#pragma unroll
        for (int r = 0; r < 4; r++) oacc[bn][r] = 0.0f;
    float m0 = -3.0e38f, m1 = -3.0e38f, l0 = 0.0f, l1 = 0.0f;

    const int wrow = warp * 16;

    __syncthreads();

    for (int kt = 0; kt < Nn_ / 32; kt++) {
        const int c0 = kt * 32;

        // ---- K tile transposed (scatter STS, no cvt) ----
#pragma unroll
        for (int i = 0; i < 4; i++) {
            int idx4 = i * 128 + tid;
            int row  = idx4 & 31;
            int d0   = (idx4 >> 5) * 4;
            uint4 kv = *(const uint4*)(kg + (size_t)(c0 + row) * HD + d0);
            Ks[d0 + 0][row] = kv.x;
            Ks[d0 + 1][row] = kv.y;
            Ks[d0 + 2][row] = kv.z;
            Ks[d0 + 3][row] = kv.w;
        }
        // ---- V tile natural: uint4 copies ----
#pragma unroll
        for (int i = 0; i < 4; i++) {
            int idx4 = i * 128 + tid;
            int row  = idx4 >> 4;
            int d0   = (idx4 & 15) * 4;
            *(uint4*)&Vs[row][d0] = *(const uint4*)(vg + (size_t)(c0 + row) * HD + d0);
        }
        __syncthreads();

        // ---- S = Q @ K^T (single tf32) ----
        float sacc[4][4];
#pragma unroll
        for (int bn = 0; bn < 4; bn++)
#pragma unroll
            for (int r = 0; r < 4; r++) sacc[bn][r] = 0.0f;

#pragma unroll
        for (int kk = 0; kk < 64; kk += 8) {
            uint32_t a0 = Qs[wrow + lr][kk + lc];
            uint32_t a1 = Qs[wrow + 8 + lr][kk + lc];
            uint32_t a2 = Qs[wrow + lr][kk + lc + 4];
            uint32_t a3 = Qs[wrow + 8 + lr][kk + lc + 4];
#pragma unroll
            for (int bn = 0; bn < 4; bn++) {
                const int col = bn * 8 + lr;
                mma_tf32(sacc[bn], a0, a1, a2, a3,
                         Ks[kk + lc][col], Ks[kk + lc + 4][col]);
            }
        }

        // ---- online softmax (rows lr, lr+8; reduce over quad lanes) ----
        float rmax0 = -3.0e38f, rmax1 = -3.0e38f;
#pragma unroll
        for (int bn = 0; bn < 4; bn++) {
            rmax0 = fmaxf(rmax0, fmaxf(sacc[bn][0], sacc[bn][1]));
            rmax1 = fmaxf(rmax1, fmaxf(sacc[bn][2], sacc[bn][3]));
        }
        rmax0 = fmaxf(rmax0, __shfl_xor_sync(0xffffffffu, rmax0, 1));
        rmax0 = fmaxf(rmax0, __shfl_xor_sync(0xffffffffu, rmax0, 2));
        rmax1 = fmaxf(rmax1, __shfl_xor_sync(0xffffffffu, rmax1, 1));
        rmax1 = fmaxf(rmax1, __shfl_xor_sync(0xffffffffu, rmax1, 2));

        const float newm0 = fmaxf(m0, rmax0);
        const float newm1 = fmaxf(m1, rmax1);
        const float fac0  = __expf(m0 - newm0);
        const float fac1  = __expf(m1 - newm1);

        float p[4][4];
        float rsum0 = 0.0f, rsum1 = 0.0f;
#pragma unroll
        for (int bn = 0; bn < 4; bn++) {
            p[bn][0] = __expf(sacc[bn][0] - newm0);
            p[bn][1] = __expf(sacc[bn][1] - newm0);
            p[bn][2] = __expf(sacc[bn][2] - newm1);
            p[bn][3] = __expf(sacc[bn][3] - newm1);
            rsum0 += p[bn][0] + p[bn][1];
            rsum1 += p[bn][2] + p[bn][3];
        }
        rsum0 += __shfl_xor_sync(0xffffffffu, rsum0, 1);
        rsum0 += __shfl_xor_sync(0xffffffffu, rsum0, 2);
        rsum1 += __shfl_xor_sync(0xffffffffu, rsum1, 1);
        rsum1 += __shfl_xor_sync(0xffffffffu, rsum1, 2);

        l0 = l0 * fac0 + rsum0;  m0 = newm0;
        l1 = l1 * fac1 + rsum1;  m1 = newm1;
#pragma unroll
        for (int bn = 0; bn < 8; bn++) {
            oacc[bn][0] *= fac0; oacc[bn][1] *= fac0;
            oacc[bn][2] *= fac1; oacc[bn][3] *= fac1;
        }

        // ---- store P (tf32) to per-warp-private rows ----
#pragma unroll
        for (int bn = 0; bn < 4; bn++) {
            Ps[wrow + lr][bn * 8 + 2 * lc]         = f2tf32(p[bn][0]);
            Ps[wrow + lr][bn * 8 + 2 * lc + 1]     = f2tf32(p[bn][1]);
            Ps[wrow + 8 + lr][bn * 8 + 2 * lc]     = f2tf32(p[bn][2]);
            Ps[wrow + 8 + lr][bn * 8 + 2 * lc + 1] = f2tf32(p[bn][3]);
        }
        __syncwarp();

        // ---- O += P @ V (single tf32) ----
#pragma unroll
        for (int kk = 0; kk < 32; kk += 8) {
            uint32_t a0 = Ps[wrow + lr][kk + lc];
            uint32_t a1 = Ps[wrow + 8 + lr][kk + lc];
            uint32_t a2 = Ps[wrow + lr][kk + lc + 4];
            uint32_t a3 = Ps[wrow + 8 + lr][kk + lc + 4];
#pragma unroll
            for (int bn = 0; bn < 8; bn++) {
                const int col = bn * 8 + lr;
                mma_tf32(oacc[bn], a0, a1, a2, a3,
                         Vs[kk + lc][col], Vs[kk + lc + 4][col]);
            }
        }
        __syncthreads();
    }

    // ---- finalize: heads (fp32) for the output projection ----
    const float inv0 = 1.0f / l0;
    const float inv1 = 1.0f / l1;
    const int row0 = r0 + wrow + lr;
    const int row1 = row0 + 8;
#pragma unroll
    for (int bn = 0; bn < 8; bn++) {
        const int col = h * HD + bn * 8 + 2 * lc;
        *(float2*)(g_heads + ((size_t)(b * Nn_ + row0) * Dd) + col) =
            make_float2(oacc[bn][0] * inv0, oacc[bn][1] * inv0);
        *(float2*)(g_heads + ((size_t)(b * Nn_ + row1) * Dd) + col) =
            make_float2(oacc[bn][2] * inv1, oacc[bn][3] * inv1);
    }
}

// ---------------------------------------------------------------------------
extern "C" void kernel_launch(void* const* d_in, const int* in_sizes, int n_in,
                              void* d_out, int out_size)
{
    // Resolve inputs BY SIZE (all element counts are distinct):
    const float *x = 0, *W_qkv = 0, *b_qkv = 0, *W_o = 0, *b_o = 0;
    for (int i = 0; i < n_in; i++) {
        const float* p = (const float*)d_in[i];
        switch (in_sizes[i]) {
            case 8388608: x     = p; break;
            case 3145728: W_qkv = p; break;
            case 3072:    b_qkv = p; break;
            case 1048576: W_o   = p; break;
            case 1024:    b_o   = p; break;
            default: break;
        }
    }
    float* out = (float*)d_out;

    const int M = Bb * Nn_;     // 8192

    // 1) QKV projection (tf32 mma) + tf32 scatter epilogue
    {
        dim3 grid(3 * Dd / 128, M / 128);   // (24, 64)
        sgemm_kernel<1><<<grid, 256>>>(x, W_qkv, b_qkv, (float*)0, M, 3 * Dd, Dd);
    }

    // 2) Attention (tf32 mma flash, single-term, static smem)
    {
        dim3 grid(Nn_ / 64, Bb * Hh);       // (16, 128)
        attn_mma_kernel<<<grid, 128>>>();
    }

    // 3) Output projection (tf32), A bound to g_heads in device code
    {
        dim3 grid(Dd / 128, M / 128);       // (8, 64)
        sgemm_kernel<2><<<grid, 256>>>((const float*)0, W_o, b_o, out, M, Dd, Dd);
    }
}

// round 10
// speedup vs baseline: 1.5469x; 1.1378x over previous
#include <cuda_runtime.h>
#include <cstdint>

#define Bb 8
#define Nn_ 1024
#define Dd 1024
#define Hh 16
#define HD 64
#define QSCALE 0.125f   // 64^-0.5, exact power of two

// Scratch (device globals: no allocations allowed)
__device__ uint32_t g_q32[Bb * Hh * Nn_ * HD];   // Q tf32 bits [bh][n][d], pre-scaled
__device__ uint32_t g_k32[Bb * Hh * Nn_ * HD];   // K tf32 bits [bh][n][d]
__device__ uint32_t g_v32[Bb * Hh * Nn_ * HD];   // V tf32 bits [bh][d][n]  (d-major!)
__device__ float    g_heads[Bb * Nn_ * Dd];      // [b][n][h*HD+d]

// ---------------------------------------------------------------------------
// helpers
// ---------------------------------------------------------------------------
__device__ __forceinline__ uint32_t f2tf32(float f) {
    uint32_t u;
    asm("cvt.rna.tf32.f32 %0, %1;" : "=r"(u) : "f"(f));
    return u;
}

__device__ __forceinline__ void mma_tf32(float c[4],
                                         uint32_t a0, uint32_t a1,
                                         uint32_t a2, uint32_t a3,
                                         uint32_t b0, uint32_t b1) {
    asm volatile(
        "mma.sync.aligned.m16n8k8.row.col.f32.tf32.tf32.f32 "
        "{%0,%1,%2,%3}, {%4,%5,%6,%7}, {%8,%9}, {%0,%1,%2,%3};"
        : "+f"(c[0]), "+f"(c[1]), "+f"(c[2]), "+f"(c[3])
        : "r"(a0), "r"(a1), "r"(a2), "r"(a3), "r"(b0), "r"(b1));
}

__device__ __forceinline__ uint32_t s2u(const void* p) {
    return (uint32_t)__cvta_generic_to_shared(p);
}

__device__ __forceinline__ void ldsm_x4(uint32_t& r0, uint32_t& r1,
                                        uint32_t& r2, uint32_t& r3,
                                        uint32_t addr) {
    asm volatile("ldmatrix.sync.aligned.m8n8.x4.shared.b16 {%0,%1,%2,%3}, [%4];"
                 : "=r"(r0), "=r"(r1), "=r"(r2), "=r"(r3) : "r"(addr));
}

// n-major B row base (words). Plain stride 20: row bases mod 32 banks are
// {0,20,8,28,16,4,24,12} for n mod 8 -> every ldmatrix matrix (8 rows x 4
// words) covers all 32 banks exactly once. NO stagger (the R9 stagger
// wrapped every 32 rows and overlapped rows 31/32 -- correctness bug).
__device__ __forceinline__ int btrow_off(int n) {
    return n * 20;
}

// ---------------------------------------------------------------------------
// TF32 tensor-core GEMM with ldmatrix fragment loads.
// Block 128x128, BK=16, 256 threads = 8 warps (2M x 4N), warp tile 64x32.
// MODE 1: QKV scatter epilogue -> g_q32 (scaled) / g_k32 [n][d] / g_v32 [d][n]
// MODE 2: A = g_heads (device bind), fp32 C + bias
// ---------------------------------------------------------------------------
template <int MODE>
__global__ __launch_bounds__(256)
void sgemm_kernel(const float* __restrict__ A,
                  const float* __restrict__ W,
                  const float* __restrict__ bias,
                  float* __restrict__ C,
                  int M, int N, int K)
{
    __shared__ uint32_t As[128][20];     // [row][k]; LDSM rows conflict-free
    __shared__ uint32_t Bt[128 * 20];    // n-major: row n at n*20

    const float* __restrict__ Ain = (MODE == 2) ? (const float*)g_heads : A;

    const int tid  = threadIdx.x;
    const int lane = tid & 31;
    const int warp = tid >> 5;
    const int warpM = warp & 1;
    const int warpN = warp >> 1;

    const int r0 = blockIdx.y * 128;
    const int c0 = blockIdx.x * 128;

    // A global-load mapping: 2 threads per row, 8 k-words each
    const int a_row = tid >> 1;
    const int a_kc  = (tid & 1) * 8;
    // B global-load mapping: thread -> one n, 8 k's (coalesced 32-bit loads)
    const int b_n  = tid & 127;
    const int b_kh = (tid >> 7) * 8;

    const float* Aptr = Ain + (size_t)(r0 + a_row) * K + a_kc;
    const float* Wcol = W + c0 + b_n;

    // ldmatrix lane constants
    const int l15   = lane & 15;
    const int lcoff = (lane >> 4) * 4;                  // A-frag col offset
    const int brow  = (lane & 7) + ((lane >> 4) << 3);  // B-frag row offset
    const int bcoff = ((lane >> 3) & 1) * 4;            // B-frag col offset

    float acc[4][4][4];
#pragma unroll
    for (int i = 0; i < 4; i++)
#pragma unroll
        for (int j = 0; j < 4; j++)
#pragma unroll
            for (int r = 0; r < 4; r++) acc[i][j][r] = 0.0f;

    const int lr = lane >> 2;
    const int lc = lane & 3;

    for (int k0 = 0; k0 < K; k0 += 16) {
        // ---- A tile: 2x float4 load, cvt, 2x uint4 STS ----
        {
            float4 v0 = *(const float4*)(Aptr + k0);
            float4 v1 = *(const float4*)(Aptr + k0 + 4);
            *(uint4*)&As[a_row][a_kc] =
                make_uint4(f2tf32(v0.x), f2tf32(v0.y), f2tf32(v0.z), f2tf32(v0.w));
            *(uint4*)&As[a_row][a_kc + 4] =
                make_uint4(f2tf32(v1.x), f2tf32(v1.y), f2tf32(v1.z), f2tf32(v1.w));
        }
        // ---- B tile: 8 coalesced scalar LDG (one n, 8 k), 2x uint4 STS ----
        {
            uint32_t bw[8];
#pragma unroll
            for (int j = 0; j < 8; j++)
                bw[j] = f2tf32(Wcol[(size_t)(k0 + b_kh + j) * N]);
            uint32_t* browp = Bt + btrow_off(b_n) + b_kh;
            *(uint4*)(browp)     = make_uint4(bw[0], bw[1], bw[2], bw[3]);
            *(uint4*)(browp + 4) = make_uint4(bw[4], bw[5], bw[6], bw[7]);
        }
        __syncthreads();

#pragma unroll
        for (int kk = 0; kk < 16; kk += 8) {
            uint32_t af[4][4];
#pragma unroll
            for (int am = 0; am < 4; am++)
                ldsm_x4(af[am][0], af[am][1], af[am][2], af[am][3],
                        s2u(&As[warpM * 64 + am * 16 + l15][kk + lcoff]));
#pragma unroll
            for (int g = 0; g < 2; g++) {
                uint32_t b0, b1, b2, b3;
                const int n0 = warpN * 32 + g * 16 + brow;
                ldsm_x4(b0, b1, b2, b3, s2u(Bt + btrow_off(n0) + kk + bcoff));
#pragma unroll
                for (int am = 0; am < 4; am++) {
                    mma_tf32(acc[am][2 * g],     af[am][0], af[am][1], af[am][2],
                             af[am][3], b0, b1);
                    mma_tf32(acc[am][2 * g + 1], af[am][0], af[am][1], af[am][2],
                             af[am][3], b2, b3);
                }
            }
        }
        __syncthreads();
    }

    // ---- epilogue ----
#pragma unroll
    for (int am = 0; am < 4; am++) {
        const int row0 = r0 + warpM * 64 + am * 16 + lr;
        const int row1 = row0 + 8;
#pragma unroll
        for (int bn = 0; bn < 4; bn++) {
            const int atomcol = c0 + warpN * 32 + bn * 8;
            const int colp = atomcol + lc * 2;
            const float b0v = bias[colp];
            const float b1v = bias[colp + 1];
            float v00 = acc[am][bn][0] + b0v, v01 = acc[am][bn][1] + b1v;
            float v10 = acc[am][bn][2] + b0v, v11 = acc[am][bn][3] + b1v;

            if (MODE == 2) {
                *(float2*)(C + (size_t)row0 * N + colp) = make_float2(v00, v01);
                *(float2*)(C + (size_t)row1 * N + colp) = make_float2(v10, v11);
            } else {
                // col -> (h, t, d): 8-col atom never crosses a 64/192 boundary
                const int h     = atomcol / 192;
                const int rem   = atomcol % 192;
                const int t     = rem / 64;          // 0=q 1=k 2=v
                const int dbase = (rem % 64) + lc * 2;
                const int b0r = row0 >> 10, n0 = row0 & 1023;
                const int b1r = row1 >> 10, n1 = row1 & 1023;

                if (t == 2) {
                    // V is d-major: [bh][d][n]
                    const size_t vb0 = ((size_t)(b0r * Hh + h) * HD + dbase) * Nn_;
                    const size_t vb1 = ((size_t)(b1r * Hh + h) * HD + dbase) * Nn_;
                    g_v32[vb0 + n0]        = f2tf32(v00);
                    g_v32[vb0 + Nn_ + n0]  = f2tf32(v01);
                    g_v32[vb1 + n1]        = f2tf32(v10);
                    g_v32[vb1 + Nn_ + n1]  = f2tf32(v11);
                } else {
                    uint32_t* dst = (t == 0) ? g_q32 : g_k32;
                    const float sc = (t == 0) ? QSCALE : 1.0f;
                    const size_t off0 = (((size_t)(b0r * Hh + h) << 10) + n0) * HD + dbase;
                    const size_t off1 = (((size_t)(b1r * Hh + h) << 10) + n1) * HD + dbase;
                    *(uint2*)(dst + off0) = make_uint2(f2tf32(v00 * sc), f2tf32(v01 * sc));
                    *(uint2*)(dst + off1) = make_uint2(f2tf32(v10 * sc), f2tf32(v11 * sc));
                }
            }
        }
    }
}

// ---------------------------------------------------------------------------
// Tensor-core flash attention, single-tf32, all fragments via ldmatrix.
// Block = (bh, 64 q-rows), 128 threads = 4 warps, K/V tiles of 32.
// Static smem 44,544 B. Layouts (all LDSM-conflict-free, plain 2D arrays):
//   Qs[64][68] [row][d]    Ks[32][68] [seq][d] (n-major for S)
//   Vs[64][36] [d][seq]    (n-major for PV; straight copy from d-major g_v32)
//   Ps[64][36] [row][seq]
// ---------------------------------------------------------------------------
__global__ __launch_bounds__(128, 4)
void attn_mma_kernel()
{
    __shared__ uint32_t Qs[64][68];
    __shared__ uint32_t Ks[32][68];
    __shared__ uint32_t Vs[64][36];
    __shared__ uint32_t Ps[64][36];

    const int tid  = threadIdx.x;
    const int lane = tid & 31;
    const int warp = tid >> 5;
    const int lr   = lane >> 2;
    const int lc   = lane & 3;

    const int bh = blockIdx.y;
    const int r0 = blockIdx.x * 64;
    const int b  = bh >> 4;
    const int h  = bh & 15;

    const uint32_t* qg = g_q32 + (size_t)bh * Nn_ * HD;      // [n][d]
    const uint32_t* kg = g_k32 + (size_t)bh * Nn_ * HD;      // [n][d]
    const uint32_t* vg = g_v32 + (size_t)bh * HD * Nn_;      // [d][n]

    // ldmatrix lane constants
    const int l15   = lane & 15;
    const int lcoff = (lane >> 4) * 4;
    const int brow  = (lane & 7) + ((lane >> 4) << 3);
    const int bcoff = ((lane >> 3) & 1) * 4;

    // ---- Q tile: straight uint4 copies ----
#pragma unroll
    for (int i = 0; i < 8; i++) {
        int idx4 = i * 128 + tid;
        int row  = idx4 >> 4;
        int d0   = (idx4 & 15) * 4;
        *(uint4*)&Qs[row][d0] = *(const uint4*)(qg + (size_t)(r0 + row) * HD + d0);
    }

    float oacc[8][4];
#pragma unroll
    for (int bn = 0; bn < 8; bn++)
#pragma unroll
        for (int r = 0; r < 4; r++) oacc[bn][r] = 0.0f;
    float m0 = -3.0e38f, m1 = -3.0e38f, l0 = 0.0f, l1 = 0.0f;

    const int wrow = warp * 16;

    __syncthreads();

    for (int kt = 0; kt < Nn_ / 32; kt++) {
        const int c0 = kt * 32;

        // ---- K tile natural [seq][d]: uint4 copies ----
#pragma unroll
        for (int i = 0; i < 4; i++) {
            int idx4 = i * 128 + tid;
            int row  = idx4 >> 4;            // 0..31
            int d0   = (idx4 & 15) * 4;
            *(uint4*)&Ks[row][d0] = *(const uint4*)(kg + (size_t)(c0 + row) * HD + d0);
        }
        // ---- V tile [d][seq]: uint4 copies from d-major global ----
#pragma unroll
        for (int i = 0; i < 4; i++) {
            int idx4 = i * 128 + tid;
            int d    = idx4 >> 3;            // 0..63
            int s4   = (idx4 & 7) * 4;       // 0..28
            *(uint4*)&Vs[d][s4] = *(const uint4*)(vg + (size_t)d * Nn_ + c0 + s4);
        }
        __syncthreads();

        // ---- S = Q @ K^T (LDSM fragments) ----
        float sacc[4][4];
#pragma unroll
        for (int bn = 0; bn < 4; bn++)
#pragma unroll
            for (int r = 0; r < 4; r++) sacc[bn][r] = 0.0f;

#pragma unroll
        for (int kk = 0; kk < 64; kk += 8) {
            uint32_t a0, a1, a2, a3;
            ldsm_x4(a0, a1, a2, a3, s2u(&Qs[wrow + l15][kk + lcoff]));
            uint32_t k0r, k1r, k2r, k3r;
            ldsm_x4(k0r, k1r, k2r, k3r, s2u(&Ks[brow][kk + bcoff]));
            mma_tf32(sacc[0], a0, a1, a2, a3, k0r, k1r);
            mma_tf32(sacc[1], a0, a1, a2, a3, k2r, k3r);
            ldsm_x4(k0r, k1r, k2r, k3r, s2u(&Ks[16 + brow][kk + bcoff]));
            mma_tf32(sacc[2], a0, a1, a2, a3, k0r, k1r);
            mma_tf32(sacc[3], a0, a1, a2, a3, k2r, k3r);
        }

        // ---- online softmax (rows lr, lr+8; reduce over quad lanes) ----
        float rmax0 = -3.0e38f, rmax1 = -3.0e38f;
#pragma unroll
        for (int bn = 0; bn < 4; bn++) {
            rmax0 = fmaxf(rmax0, fmaxf(sacc[bn][0], sacc[bn][1]));
            rmax1 = fmaxf(rmax1, fmaxf(sacc[bn][2], sacc[bn][3]));
        }
        rmax0 = fmaxf(rmax0, __shfl_xor_sync(0xffffffffu, rmax0, 1));
        rmax0 = fmaxf(rmax0, __shfl_xor_sync(0xffffffffu, rmax0, 2));
        rmax1 = fmaxf(rmax1, __shfl_xor_sync(0xffffffffu, rmax1, 1));
        rmax1 = fmaxf(rmax1, __shfl_xor_sync(0xffffffffu, rmax1, 2));

        const float newm0 = fmaxf(m0, rmax0);
        const float newm1 = fmaxf(m1, rmax1);
        const float fac0  = __expf(m0 - newm0);
        const float fac1  = __expf(m1 - newm1);

        float p[4][4];
        float rsum0 = 0.0f, rsum1 = 0.0f;
#pragma unroll
        for (int bn = 0; bn < 4; bn++) {
            p[bn][0] = __expf(sacc[bn][0] - newm0);
            p[bn][1] = __expf(sacc[bn][1] - newm0);
            p[bn][2] = __expf(sacc[bn][2] - newm1);
            p[bn][3] = __expf(sacc[bn][3] - newm1);
            rsum0 += p[bn][0] + p[bn][1];
            rsum1 += p[bn][2] + p[bn][3];
        }
        rsum0 += __shfl_xor_sync(0xffffffffu, rsum0, 1);
        rsum0 += __shfl_xor_sync(0xffffffffu, rsum0, 2);
        rsum1 += __shfl_xor_sync(0xffffffffu, rsum1, 1);
        rsum1 += __shfl_xor_sync(0xffffffffu, rsum1, 2);

        l0 = l0 * fac0 + rsum0;  m0 = newm0;
        l1 = l1 * fac1 + rsum1;  m1 = newm1;
#pragma unroll
        for (int bn = 0; bn < 8; bn++) {
            oacc[bn][0] *= fac0; oacc[bn][1] *= fac0;
            oacc[bn][2] *= fac1; oacc[bn][3] *= fac1;
        }

        // ---- store P (tf32) to per-warp-private rows ----
#pragma unroll
        for (int bn = 0; bn < 4; bn++) {
            Ps[wrow + lr][bn * 8 + 2 * lc]         = f2tf32(p[bn][0]);
            Ps[wrow + lr][bn * 8 + 2 * lc + 1]     = f2tf32(p[bn][1]);
            Ps[wrow + 8 + lr][bn * 8 + 2 * lc]     = f2tf32(p[bn][2]);
            Ps[wrow + 8 + lr][bn * 8 + 2 * lc + 1] = f2tf32(p[bn][3]);
        }
        __syncwarp();

        // ---- O += P @ V (LDSM fragments) ----
#pragma unroll
        for (int kk = 0; kk < 32; kk += 8) {
            uint32_t a0, a1, a2, a3;
            ldsm_x4(a0, a1, a2, a3, s2u(&Ps[wrow + l15][kk + lcoff]));
#pragma unroll
            for (int g = 0; g < 4; g++) {
                uint32_t v0, v1, v2, v3;
                ldsm_x4(v0, v1, v2, v3, s2u(&Vs[g * 16 + brow][kk + bcoff]));
                mma_tf32(oacc[2 * g],     a0, a1, a2, a3, v0, v1);
                mma_tf32(oacc[2 * g + 1], a0, a1, a2, a3, v2, v3);
            }
        }
        __syncthreads();
    }

    // ---- finalize: heads (fp32) for the output projection ----
    const float inv0 = 1.0f / l0;
    const float inv1 = 1.0f / l1;
    const int row0 = r0 + wrow + lr;
    const int row1 = row0 + 8;
#pragma unroll
    for (int bn = 0; bn < 8; bn++) {
        const int col = h * HD + bn * 8 + 2 * lc;
        *(float2*)(g_heads + ((size_t)(b * Nn_ + row0) * Dd) + col) =
            make_float2(oacc[bn][0] * inv0, oacc[bn][1] * inv0);
        *(float2*)(g_heads + ((size_t)(b * Nn_ + row1) * Dd) + col) =
            make_float2(oacc[bn][2] * inv1, oacc[bn][3] * inv1);
    }
}

// ---------------------------------------------------------------------------
extern "C" void kernel_launch(void* const* d_in, const int* in_sizes, int n_in,
                              void* d_out, int out_size)
{
    // Resolve inputs BY SIZE (all element counts are distinct):
    const float *x = 0, *W_qkv = 0, *b_qkv = 0, *W_o = 0, *b_o = 0;
    for (int i = 0; i < n_in; i++) {
        const float* p = (const float*)d_in[i];
        switch (in_sizes[i]) {
            case 8388608: x     = p; break;
            case 3145728: W_qkv = p; break;
            case 3072:    b_qkv = p; break;
            case 1048576: W_o   = p; break;
            case 1024:    b_o   = p; break;
            default: break;
        }
    }
    float* out = (float*)d_out;

    const int M = Bb * Nn_;     // 8192

    // 1) QKV projection (tf32 mma + ldmatrix) + tf32 scatter epilogue
    {
        dim3 grid(3 * Dd / 128, M / 128);   // (24, 64)
        sgemm_kernel<1><<<grid, 256>>>(x, W_qkv, b_qkv, (float*)0, M, 3 * Dd, Dd);
    }

    // 2) Attention (tf32 mma flash, ldmatrix fragments)
    {
        dim3 grid(Nn_ / 64, Bb * Hh);       // (16, 128)
        attn_mma_kernel<<<grid, 128>>>();
    }

    // 3) Output projection
    {
        dim3 grid(Dd / 128, M / 128);       // (8, 64)
        sgemm_kernel<2><<<grid, 256>>>((const float*)0, W_o, b_o, out, M, Dd, Dd);
    }
}

// round 12
// speedup vs baseline: 2.0902x; 1.3512x over previous
#include <cuda_runtime.h>
#include <cuda_fp16.h>
#include <cstdint>

#define Bb 8
#define Nn_ 1024
#define Dd 1024
#define Hh 16
#define HD 64
#define QSCALE 0.125f   // 64^-0.5, exact power of two

// Scratch (device globals: no allocations allowed)
__device__ __half g_q16[Bb * Hh * Nn_ * HD];   // Q fp16 [bh][n][d], pre-scaled
__device__ __half g_k16[Bb * Hh * Nn_ * HD];   // K fp16 [bh][n][d]
__device__ __half g_v16[Bb * Hh * Nn_ * HD];   // V fp16 [bh][d][n]  (d-major!)
__device__ float  g_heads[Bb * Nn_ * Dd];      // [b][n][h*HD+d]

// ---------------------------------------------------------------------------
// helpers
// ---------------------------------------------------------------------------
__device__ __forceinline__ uint32_t pkh(float a, float b) {   // {lo=a, hi=b}
    uint32_t r;
    asm("cvt.rn.f16x2.f32 %0, %1, %2;" : "=r"(r) : "f"(b), "f"(a));
    return r;
}

__device__ __forceinline__ void mma_f16(float c[4],
                                        uint32_t a0, uint32_t a1,
                                        uint32_t a2, uint32_t a3,
                                        uint32_t b0, uint32_t b1) {
    asm volatile(
        "mma.sync.aligned.m16n8k16.row.col.f32.f16.f16.f32 "
        "{%0,%1,%2,%3}, {%4,%5,%6,%7}, {%8,%9}, {%0,%1,%2,%3};"
        : "+f"(c[0]), "+f"(c[1]), "+f"(c[2]), "+f"(c[3])
        : "r"(a0), "r"(a1), "r"(a2), "r"(a3), "r"(b0), "r"(b1));
}

__device__ __forceinline__ uint32_t s2u(const void* p) {
    return (uint32_t)__cvta_generic_to_shared(p);
}

__device__ __forceinline__ void ldsm_x4(uint32_t& r0, uint32_t& r1,
                                        uint32_t& r2, uint32_t& r3,
                                        uint32_t addr) {
    asm volatile("ldmatrix.sync.aligned.m8n8.x4.shared.b16 {%0,%1,%2,%3}, [%4];"
                 : "=r"(r0), "=r"(r1), "=r"(r2), "=r"(r3) : "r"(addr));
}

// ---------------------------------------------------------------------------
// fp16 tensor-core GEMM: C[M,N] = A[M,K] @ W[K,N] + bias[N]
// Block 128x128, BK=32, 256 threads = 8 warps (2M x 4N), warp tile 64x32,
// mma.m16n8k16.f16 with fp32 accumulate (fp16 eps == tf32 eps == 2^-11).
// Smem strides 40 halves (80B; 5*r mod 8 distinct -> LDSM conflict-free).
// MODE 1: QKV scatter epilogue -> g_q16 (scaled) / g_k16 [n][d] / g_v16 [d][n]
// MODE 2: A = g_heads (device bind), fp32 C + bias
// ---------------------------------------------------------------------------
template <int MODE>
__global__ __launch_bounds__(256)
void sgemm_kernel(const float* __restrict__ A,
                  const float* __restrict__ W,
                  const float* __restrict__ bias,
                  float* __restrict__ C,
                  int M, int N, int K)
{
    __shared__ __half Ah[128][40];   // [row][k]
    __shared__ __half Bh[128][40];   // [n][k]  (n-major)

    const float* __restrict__ Ain = (MODE == 2) ? (const float*)g_heads : A;

    const int tid  = threadIdx.x;
    const int lane = tid & 31;
    const int warp = tid >> 5;
    const int warpM = warp & 1;
    const int warpN = warp >> 1;

    const int r0 = blockIdx.y * 128;
    const int c0 = blockIdx.x * 128;

    // A loader: 2 threads/row, 16 floats each
    const int a_row = tid >> 1;
    const int a_kc  = (tid & 1) * 16;
    // B loader: thread -> one n, 16 k's (coalesced 32-bit LDG)
    const int b_n  = tid & 127;
    const int b_kh = (tid >> 7) * 16;

    const float* Aptr = Ain + (size_t)(r0 + a_row) * K + a_kc;
    const float* Wcol = W + c0 + b_n;

    // ldmatrix lane constants
    const int l15   = lane & 15;
    const int lcoff = (lane >> 4) * 8;                  // A-frag k offset (halves)
    const int brow  = (lane & 7) + ((lane >> 4) << 3);  // B-frag n-row offset
    const int bcoff = ((lane >> 3) & 1) * 8;            // B-frag k offset (halves)

    float acc[4][4][4];
#pragma unroll
    for (int i = 0; i < 4; i++)
#pragma unroll
        for (int j = 0; j < 4; j++)
#pragma unroll
            for (int r = 0; r < 4; r++) acc[i][j][r] = 0.0f;

    const int lr = lane >> 2;
    const int lc = lane & 3;

    for (int k0 = 0; k0 < K; k0 += 32) {
        // ---- A tile: [128 rows][32 k] fp32 -> fp16 ----
        {
            float4 v0 = *(const float4*)(Aptr + k0);
            float4 v1 = *(const float4*)(Aptr + k0 + 4);
            float4 v2 = *(const float4*)(Aptr + k0 + 8);
            float4 v3 = *(const float4*)(Aptr + k0 + 12);
            uint32_t* dst = (uint32_t*)&Ah[a_row][a_kc];
            *(uint4*)dst = make_uint4(pkh(v0.x, v0.y), pkh(v0.z, v0.w),
                                      pkh(v1.x, v1.y), pkh(v1.z, v1.w));
            *(uint4*)(dst + 4) = make_uint4(pkh(v2.x, v2.y), pkh(v2.z, v2.w),
                                            pkh(v3.x, v3.y), pkh(v3.z, v3.w));
        }
        // ---- B tile: [128 n][32 k] transpose gather, fp32 -> fp16 ----
        {
            float w[16];
#pragma unroll
            for (int j = 0; j < 16; j++)
                w[j] = Wcol[(size_t)(k0 + b_kh + j) * N];
            uint32_t* dst = (uint32_t*)&Bh[b_n][b_kh];
            *(uint4*)dst = make_uint4(pkh(w[0], w[1]), pkh(w[2], w[3]),
                                      pkh(w[4], w[5]), pkh(w[6], w[7]));
            *(uint4*)(dst + 4) = make_uint4(pkh(w[8], w[9]), pkh(w[10], w[11]),
                                            pkh(w[12], w[13]), pkh(w[14], w[15]));
        }
        __syncthreads();

#pragma unroll
        for (int kk = 0; kk < 32; kk += 16) {
            uint32_t af[4][4];
#pragma unroll
            for (int am = 0; am < 4; am++)
                ldsm_x4(af[am][0], af[am][1], af[am][2], af[am][3],
                        s2u(&Ah[warpM * 64 + am * 16 + l15][kk + lcoff]));
#pragma unroll
            for (int g = 0; g < 2; g++) {
                uint32_t b0, b1, b2, b3;
                ldsm_x4(b0, b1, b2, b3,
                        s2u(&Bh[warpN * 32 + g * 16 + brow][kk + bcoff]));
#pragma unroll
                for (int am = 0; am < 4; am++) {
                    mma_f16(acc[am][2 * g],     af[am][0], af[am][1], af[am][2],
                            af[am][3], b0, b1);
                    mma_f16(acc[am][2 * g + 1], af[am][0], af[am][1], af[am][2],
                            af[am][3], b2, b3);
                }
            }
        }
        __syncthreads();
    }

    // ---- epilogue (C layout of m16n8k16 == m16n8k8: rows lr/lr+8, cols 2lc) ----
#pragma unroll
    for (int am = 0; am < 4; am++) {
        const int row0 = r0 + warpM * 64 + am * 16 + lr;
        const int row1 = row0 + 8;
#pragma unroll
        for (int bn = 0; bn < 4; bn++) {
            const int atomcol = c0 + warpN * 32 + bn * 8;
            const int colp = atomcol + lc * 2;
            const float b0v = bias[colp];
            const float b1v = bias[colp + 1];
            float v00 = acc[am][bn][0] + b0v, v01 = acc[am][bn][1] + b1v;
            float v10 = acc[am][bn][2] + b0v, v11 = acc[am][bn][3] + b1v;

            if (MODE == 2) {
                *(float2*)(C + (size_t)row0 * N + colp) = make_float2(v00, v01);
                *(float2*)(C + (size_t)row1 * N + colp) = make_float2(v10, v11);
            } else {
                // col -> (h, t, d): 8-col atom never crosses a 64/192 boundary
                const int h     = atomcol / 192;
                const int rem   = atomcol % 192;
                const int t     = rem / 64;          // 0=q 1=k 2=v
                const int dbase = (rem % 64) + lc * 2;
                const int b0r = row0 >> 10, n0 = row0 & 1023;
                const int b1r = row1 >> 10, n1 = row1 & 1023;

                if (t == 2) {
                    // V d-major: [bh][d][n]
                    const size_t vb0 = ((size_t)(b0r * Hh + h) * HD + dbase) * Nn_;
                    const size_t vb1 = ((size_t)(b1r * Hh + h) * HD + dbase) * Nn_;
                    g_v16[vb0 + n0]       = __float2half_rn(v00);
                    g_v16[vb0 + Nn_ + n0] = __float2half_rn(v01);
                    g_v16[vb1 + n1]       = __float2half_rn(v10);
                    g_v16[vb1 + Nn_ + n1] = __float2half_rn(v11);
                } else {
                    __half* dst = (t == 0) ? g_q16 : g_k16;
                    const float sc = (t == 0) ? QSCALE : 1.0f;
                    const size_t off0 = (((size_t)(b0r * Hh + h) << 10) + n0) * HD + dbase;
                    const size_t off1 = (((size_t)(b1r * Hh + h) << 10) + n1) * HD + dbase;
                    *(uint32_t*)(dst + off0) = pkh(v00 * sc, v01 * sc);
                    *(uint32_t*)(dst + off1) = pkh(v10 * sc, v11 * sc);
                }
            }
        }
    }
}

// ---------------------------------------------------------------------------
// fp16 tensor-core flash attention (structure identical to passing R10,
// k16 fragments). Block = (bh, 64 q-rows), 128 threads = 4 warps, K/V tile 32.
// Static smem 24,064 B. Strides: 72 halves (9*r mod 8 distinct) and
// 40 halves (5*r mod 8 distinct) -> all LDSM conflict-free.
//   Qs[64][72] [row][d]   Ks[32][72] [seq][d]
//   Vs[64][40] [d][seq]   Ps[64][40] [row][seq]
// ---------------------------------------------------------------------------
__global__ __launch_bounds__(128, 4)
void attn_mma_kernel()
{
    __shared__ __half Qs[64][72];
    __shared__ __half Ks[32][72];
    __shared__ __half Vs[64][40];
    __shared__ __half Ps[64][40];

    const int tid  = threadIdx.x;
    const int lane = tid & 31;
    const int warp = tid >> 5;
    const int lr   = lane >> 2;
    const int lc   = lane & 3;

    const int bh = blockIdx.y;
    const int r0 = blockIdx.x * 64;
    const int b  = bh >> 4;
    const int h  = bh & 15;

    const __half* qg = g_q16 + (size_t)bh * Nn_ * HD;    // [n][d]
    const __half* kg = g_k16 + (size_t)bh * Nn_ * HD;    // [n][d]
    const __half* vg = g_v16 + (size_t)bh * HD * Nn_;    // [d][n]

    const int l15   = lane & 15;
    const int lcoff = (lane >> 4) * 8;
    const int brow  = (lane & 7) + ((lane >> 4) << 3);
    const int bcoff = ((lane >> 3) & 1) * 8;

    // ---- Q tile: 64 rows x 64 halves = 8 uint4 per row ----
#pragma unroll
    for (int i = 0; i < 4; i++) {
        int idx4 = i * 128 + tid;            // 0..511
        int row  = idx4 >> 3;
        int c8   = (idx4 & 7) * 8;           // halves
        *(uint4*)&Qs[row][c8] = *(const uint4*)(qg + (size_t)(r0 + row) * HD + c8);
    }

    float oacc[8][4];
#pragma unroll
    for (int bn = 0; bn < 8; bn++)
#pragma unroll
        for (int r = 0; r < 4; r++) oacc[bn][r] = 0.0f;
    float m0 = -3.0e38f, m1 = -3.0e38f, l0 = 0.0f, l1 = 0.0f;

    const int wrow = warp * 16;

    __syncthreads();

    for (int kt = 0; kt < Nn_ / 32; kt++) {
        const int c0 = kt * 32;

        // ---- K tile [seq][d]: 32 rows x 8 uint4 ----
#pragma unroll
        for (int i = 0; i < 2; i++) {
            int idx4 = i * 128 + tid;        // 0..255
            int row  = idx4 >> 3;
            int c8   = (idx4 & 7) * 8;
            *(uint4*)&Ks[row][c8] =
                *(const uint4*)(kg + (size_t)(c0 + row) * HD + c8);
        }
        // ---- V tile [d][seq]: 64 rows x 4 uint4 ----
#pragma unroll
        for (int i = 0; i < 2; i++) {
            int idx4 = i * 128 + tid;        // 0..255
            int d    = idx4 >> 2;
            int s8   = (idx4 & 3) * 8;
            *(uint4*)&Vs[d][s8] =
                *(const uint4*)(vg + (size_t)d * Nn_ + c0 + s8);
        }
        __syncthreads();

        // ---- S = Q @ K^T (fp16 k16) ----
        float sacc[4][4];
#pragma unroll
        for (int bn = 0; bn < 4; bn++)
#pragma unroll
            for (int r = 0; r < 4; r++) sacc[bn][r] = 0.0f;

#pragma unroll
        for (int kk = 0; kk < 64; kk += 16) {
            uint32_t a0, a1, a2, a3;
            ldsm_x4(a0, a1, a2, a3, s2u(&Qs[wrow + l15][kk + lcoff]));
            uint32_t k0r, k1r, k2r, k3r;
            ldsm_x4(k0r, k1r, k2r, k3r, s2u(&Ks[brow][kk + bcoff]));
            mma_f16(sacc[0], a0, a1, a2, a3, k0r, k1r);
            mma_f16(sacc[1], a0, a1, a2, a3, k2r, k3r);
            ldsm_x4(k0r, k1r, k2r, k3r, s2u(&Ks[16 + brow][kk + bcoff]));
            mma_f16(sacc[2], a0, a1, a2, a3, k0r, k1r);
            mma_f16(sacc[3], a0, a1, a2, a3, k2r, k3r);
        }

        // ---- online softmax (rows lr, lr+8; reduce over quad lanes) ----
        float rmax0 = -3.0e38f, rmax1 = -3.0e38f;
#pragma unroll
        for (int bn = 0; bn < 4; bn++) {
            rmax0 = fmaxf(rmax0, fmaxf(sacc[bn][0], sacc[bn][1]));
            rmax1 = fmaxf(rmax1, fmaxf(sacc[bn][2], sacc[bn][3]));
        }
        rmax0 = fmaxf(rmax0, __shfl_xor_sync(0xffffffffu, rmax0, 1));
        rmax0 = fmaxf(rmax0, __shfl_xor_sync(0xffffffffu, rmax0, 2));
        rmax1 = fmaxf(rmax1, __shfl_xor_sync(0xffffffffu, rmax1, 1));
        rmax1 = fmaxf(rmax1, __shfl_xor_sync(0xffffffffu, rmax1, 2));

        const float newm0 = fmaxf(m0, rmax0);
        const float newm1 = fmaxf(m1, rmax1);
        const float fac0  = __expf(m0 - newm0);
        const float fac1  = __expf(m1 - newm1);

        float p[4][4];
        float rsum0 = 0.0f, rsum1 = 0.0f;
#pragma unroll
        for (int bn = 0; bn < 4; bn++) {
            p[bn][0] = __expf(sacc[bn][0] - newm0);
            p[bn][1] = __expf(sacc[bn][1] - newm0);
            p[bn][2] = __expf(sacc[bn][2] - newm1);
            p[bn][3] = __expf(sacc[bn][3] - newm1);
            rsum0 += p[bn][0] + p[bn][1];
            rsum1 += p[bn][2] + p[bn][3];
        }
        rsum0 += __shfl_xor_sync(0xffffffffu, rsum0, 1);
        rsum0 += __shfl_xor_sync(0xffffffffu, rsum0, 2);
        rsum1 += __shfl_xor_sync(0xffffffffu, rsum1, 1);
        rsum1 += __shfl_xor_sync(0xffffffffu, rsum1, 2);

        l0 = l0 * fac0 + rsum0;  m0 = newm0;
        l1 = l1 * fac1 + rsum1;  m1 = newm1;
#pragma unroll
        for (int bn = 0; bn < 8; bn++) {
            oacc[bn][0] *= fac0; oacc[bn][1] *= fac0;
            oacc[bn][2] *= fac1; oacc[bn][3] *= fac1;
        }

        // ---- store P (fp16 pairs, one 32-bit STS per pair) ----
#pragma unroll
        for (int bn = 0; bn < 4; bn++) {
            *(uint32_t*)&Ps[wrow + lr][bn * 8 + 2 * lc]     = pkh(p[bn][0], p[bn][1]);
            *(uint32_t*)&Ps[wrow + 8 + lr][bn * 8 + 2 * lc] = pkh(p[bn][2], p[bn][3]);
        }
        __syncwarp();

        // ---- O += P @ V (fp16 k16) ----
#pragma unroll
        for (int kk = 0; kk < 32; kk += 16) {
            uint32_t a0, a1, a2, a3;
            ldsm_x4(a0, a1, a2, a3, s2u(&Ps[wrow + l15][kk + lcoff]));
#pragma unroll
            for (int g = 0; g < 4; g++) {
                uint32_t v0, v1, v2, v3;
                ldsm_x4(v0, v1, v2, v3, s2u(&Vs[g * 16 + brow][kk + bcoff]));
                mma_f16(oacc[2 * g],     a0, a1, a2, a3, v0, v1);
                mma_f16(oacc[2 * g + 1], a0, a1, a2, a3, v2, v3);
            }
        }
        __syncthreads();
    }

    // ---- finalize: heads (fp32) for the output projection ----
    const float inv0 = 1.0f / l0;
    const float inv1 = 1.0f / l1;
    const int row0 = r0 + wrow + lr;
    const int row1 = row0 + 8;
#pragma unroll
    for (int bn = 0; bn < 8; bn++) {
        const int col = h * HD + bn * 8 + 2 * lc;
        *(float2*)(g_heads + ((size_t)(b * Nn_ + row0) * Dd) + col) =
            make_float2(oacc[bn][0] * inv0, oacc[bn][1] * inv0);
        *(float2*)(g_heads + ((size_t)(b * Nn_ + row1) * Dd) + col) =
            make_float2(oacc[bn][2] * inv1, oacc[bn][3] * inv1);
    }
}

// ---------------------------------------------------------------------------
extern "C" void kernel_launch(void* const* d_in, const int* in_sizes, int n_in,
                              void* d_out, int out_size)
{
    // Resolve inputs BY SIZE (all element counts are distinct):
    const float *x = 0, *W_qkv = 0, *b_qkv = 0, *W_o = 0, *b_o = 0;
    for (int i = 0; i < n_in; i++) {
        const float* p = (const float*)d_in[i];
        switch (in_sizes[i]) {
            case 8388608: x     = p; break;
            case 3145728: W_qkv = p; break;
            case 3072:    b_qkv = p; break;
            case 1048576: W_o   = p; break;
            case 1024:    b_o   = p; break;
            default: break;
        }
    }
    float* out = (float*)d_out;

    const int M = Bb * Nn_;     // 8192

    // 1) QKV projection (fp16 k16 mma) + fp16 scatter epilogue
    {
        dim3 grid(3 * Dd / 128, M / 128);   // (24, 64)
        sgemm_kernel<1><<<grid, 256>>>(x, W_qkv, b_qkv, (float*)0, M, 3 * Dd, Dd);
    }

    // 2) Attention (fp16 k16 mma flash, ldmatrix fragments)
    {
        dim3 grid(Nn_ / 64, Bb * Hh);       // (16, 128)
        attn_mma_kernel<<<grid, 128>>>();
    }

    // 3) Output projection (fp16 k16 mma)
    {
        dim3 grid(Dd / 128, M / 128);       // (8, 64)
        sgemm_kernel<2><<<grid, 256>>>((const float*)0, W_o, b_o, out, M, Dd, Dd);
    }
}

// round 13
// speedup vs baseline: 2.6168x; 1.2519x over previous
#include <cuda_runtime.h>
#include <cuda_fp16.h>
#include <cstdint>

#define Bb 8
#define Nn_ 1024
#define Dd 1024
#define Hh 16
#define HD 64
#define QSCALE 0.125f   // 64^-0.5, exact power of two

// Scratch (device globals: no allocations allowed)
__device__ __half g_q16[Bb * Hh * Nn_ * HD];   // Q fp16 [bh][n][d], pre-scaled
__device__ __half g_k16[Bb * Hh * Nn_ * HD];   // K fp16 [bh][n][d]
__device__ __half g_v16[Bb * Hh * Nn_ * HD];   // V fp16 [bh][d][n]  (d-major!)
__device__ float  g_heads[Bb * Nn_ * Dd];      // [b][n][h*HD+d]

// ---------------------------------------------------------------------------
// helpers
// ---------------------------------------------------------------------------
__device__ __forceinline__ uint32_t pkh(float a, float b) {   // {lo=a, hi=b}
    uint32_t r;
    asm("cvt.rn.f16x2.f32 %0, %1, %2;" : "=r"(r) : "f"(b), "f"(a));
    return r;
}

__device__ __forceinline__ void mma_f16(float c[4],
                                        uint32_t a0, uint32_t a1,
                                        uint32_t a2, uint32_t a3,
                                        uint32_t b0, uint32_t b1) {
    asm volatile(
        "mma.sync.aligned.m16n8k16.row.col.f32.f16.f16.f32 "
        "{%0,%1,%2,%3}, {%4,%5,%6,%7}, {%8,%9}, {%0,%1,%2,%3};"
        : "+f"(c[0]), "+f"(c[1]), "+f"(c[2]), "+f"(c[3])
        : "r"(a0), "r"(a1), "r"(a2), "r"(a3), "r"(b0), "r"(b1));
}

__device__ __forceinline__ uint32_t s2u(const void* p) {
    return (uint32_t)__cvta_generic_to_shared(p);
}

__device__ __forceinline__ void ldsm_x4(uint32_t& r0, uint32_t& r1,
                                        uint32_t& r2, uint32_t& r3,
                                        uint32_t addr) {
    asm volatile("ldmatrix.sync.aligned.m8n8.x4.shared.b16 {%0,%1,%2,%3}, [%4];"
                 : "=r"(r0), "=r"(r1), "=r"(r2), "=r"(r3) : "r"(addr));
}

// ---------------------------------------------------------------------------
// fp16 tensor-core GEMM, software-pipelined:
// double-buffered fp16 smem tiles + register prefetch of next K-stage's
// globals issued BEFORE the current stage's MMAs (hides ~600cyc LDG latency).
// Block 128x128, BK=32, 256 threads = 8 warps (2M x 4N), warp tile 64x32.
// MODE 1: QKV scatter epilogue -> g_q16 (scaled) / g_k16 [n][d] / g_v16 [d][n]
// MODE 2: A = g_heads (device bind), fp32 C + bias
// ---------------------------------------------------------------------------
template <int MODE>
__global__ __launch_bounds__(256)
void sgemm_kernel(const float* __restrict__ A,
                  const float* __restrict__ W,
                  const float* __restrict__ bias,
                  float* __restrict__ C,
                  int M, int N, int K)
{
    __shared__ __half Ah[2][128][40];   // [buf][row][k]   20,480 B
    __shared__ __half Bh[2][128][40];   // [buf][n][k]     20,480 B

    const float* __restrict__ Ain = (MODE == 2) ? (const float*)g_heads : A;

    const int tid  = threadIdx.x;
    const int lane = tid & 31;
    const int warp = tid >> 5;
    const int warpM = warp & 1;
    const int warpN = warp >> 1;

    const int r0 = blockIdx.y * 128;
    const int c0 = blockIdx.x * 128;

    // A loader: 2 threads/row, 16 floats each
    const int a_row = tid >> 1;
    const int a_kc  = (tid & 1) * 16;
    // B loader: thread -> one n, 16 k's (coalesced 32-bit LDG)
    const int b_n  = tid & 127;
    const int b_kh = (tid >> 7) * 16;

    const float* Aptr = Ain + (size_t)(r0 + a_row) * K + a_kc;
    const float* Wcol = W + c0 + b_n;

    // ldmatrix lane constants
    const int l15   = lane & 15;
    const int lcoff = (lane >> 4) * 8;
    const int brow  = (lane & 7) + ((lane >> 4) << 3);
    const int bcoff = ((lane >> 3) & 1) * 8;

    float acc[4][4][4];
#pragma unroll
    for (int i = 0; i < 4; i++)
#pragma unroll
        for (int j = 0; j < 4; j++)
#pragma unroll
            for (int r = 0; r < 4; r++) acc[i][j][r] = 0.0f;

    const int lr = lane >> 2;
    const int lc = lane & 3;

    // prefetch registers
    float4 pa0, pa1, pa2, pa3;
    float  pw[16];

#define GLOAD(k0) do {                                                       \
        pa0 = *(const float4*)(Aptr + (k0));                                 \
        pa1 = *(const float4*)(Aptr + (k0) + 4);                             \
        pa2 = *(const float4*)(Aptr + (k0) + 8);                             \
        pa3 = *(const float4*)(Aptr + (k0) + 12);                            \
        _Pragma("unroll")                                                    \
        for (int j = 0; j < 16; j++)                                         \
            pw[j] = Wcol[(size_t)((k0) + b_kh + j) * N];                     \
    } while (0)

#define SSTORE(buf) do {                                                     \
        uint32_t* da = (uint32_t*)&Ah[buf][a_row][a_kc];                     \
        *(uint4*)da = make_uint4(pkh(pa0.x, pa0.y), pkh(pa0.z, pa0.w),       \
                                 pkh(pa1.x, pa1.y), pkh(pa1.z, pa1.w));      \
        *(uint4*)(da + 4) = make_uint4(pkh(pa2.x, pa2.y), pkh(pa2.z, pa2.w), \
                                       pkh(pa3.x, pa3.y), pkh(pa3.z, pa3.w));\
        uint32_t* db = (uint32_t*)&Bh[buf][b_n][b_kh];                       \
        *(uint4*)db = make_uint4(pkh(pw[0], pw[1]), pkh(pw[2], pw[3]),       \
                                 pkh(pw[4], pw[5]), pkh(pw[6], pw[7]));      \
        *(uint4*)(db + 4) = make_uint4(pkh(pw[8], pw[9]), pkh(pw[10], pw[11]),\
                                       pkh(pw[12], pw[13]), pkh(pw[14], pw[15]));\
    } while (0)

    // prologue: stage 0
    GLOAD(0);
    SSTORE(0);
    __syncthreads();

    const int NS = K / 32;
    int buf = 0;
    for (int stage = 0; stage < NS; stage++) {
        // issue next stage's global loads BEFORE consuming current stage
        if (stage + 1 < NS) GLOAD((stage + 1) * 32);

#pragma unroll
        for (int kk = 0; kk < 32; kk += 16) {
            uint32_t af[4][4];
#pragma unroll
            for (int am = 0; am < 4; am++)
                ldsm_x4(af[am][0], af[am][1], af[am][2], af[am][3],
                        s2u(&Ah[buf][warpM * 64 + am * 16 + l15][kk + lcoff]));
#pragma unroll
            for (int g = 0; g < 2; g++) {
                uint32_t b0, b1, b2, b3;
                ldsm_x4(b0, b1, b2, b3,
                        s2u(&Bh[buf][warpN * 32 + g * 16 + brow][kk + bcoff]));
#pragma unroll
                for (int am = 0; am < 4; am++) {
                    mma_f16(acc[am][2 * g],     af[am][0], af[am][1], af[am][2],
                            af[am][3], b0, b1);
                    mma_f16(acc[am][2 * g + 1], af[am][0], af[am][1], af[am][2],
                            af[am][3], b2, b3);
                }
            }
        }

        if (stage + 1 < NS) SSTORE(buf ^ 1);
        __syncthreads();
        buf ^= 1;
    }
#undef GLOAD
#undef SSTORE

    // ---- epilogue ----
#pragma unroll
    for (int am = 0; am < 4; am++) {
        const int row0 = r0 + warpM * 64 + am * 16 + lr;
        const int row1 = row0 + 8;
#pragma unroll
        for (int bn = 0; bn < 4; bn++) {
            const int atomcol = c0 + warpN * 32 + bn * 8;
            const int colp = atomcol + lc * 2;
            const float b0v = bias[colp];
            const float b1v = bias[colp + 1];
            float v00 = acc[am][bn][0] + b0v, v01 = acc[am][bn][1] + b1v;
            float v10 = acc[am][bn][2] + b0v, v11 = acc[am][bn][3] + b1v;

            if (MODE == 2) {
                *(float2*)(C + (size_t)row0 * N + colp) = make_float2(v00, v01);
                *(float2*)(C + (size_t)row1 * N + colp) = make_float2(v10, v11);
            } else {
                const int h     = atomcol / 192;
                const int rem   = atomcol % 192;
                const int t     = rem / 64;          // 0=q 1=k 2=v
                const int dbase = (rem % 64) + lc * 2;
                const int b0r = row0 >> 10, n0 = row0 & 1023;
                const int b1r = row1 >> 10, n1 = row1 & 1023;

                if (t == 2) {
                    const size_t vb0 = ((size_t)(b0r * Hh + h) * HD + dbase) * Nn_;
                    const size_t vb1 = ((size_t)(b1r * Hh + h) * HD + dbase) * Nn_;
                    g_v16[vb0 + n0]       = __float2half_rn(v00);
                    g_v16[vb0 + Nn_ + n0] = __float2half_rn(v01);
                    g_v16[vb1 + n1]       = __float2half_rn(v10);
                    g_v16[vb1 + Nn_ + n1] = __float2half_rn(v11);
                } else {
                    __half* dst = (t == 0) ? g_q16 : g_k16;
                    const float sc = (t == 0) ? QSCALE : 1.0f;
                    const size_t off0 = (((size_t)(b0r * Hh + h) << 10) + n0) * HD + dbase;
                    const size_t off1 = (((size_t)(b1r * Hh + h) << 10) + n1) * HD + dbase;
                    *(uint32_t*)(dst + off0) = pkh(v00 * sc, v01 * sc);
                    *(uint32_t*)(dst + off1) = pkh(v10 * sc, v11 * sc);
                }
            }
        }
    }
}

// ---------------------------------------------------------------------------
// fp16 tensor-core flash attention (UNCHANGED from R12 -- passing).
// ---------------------------------------------------------------------------
__global__ __launch_bounds__(128, 4)
void attn_mma_kernel()
{
    __shared__ __half Qs[64][72];
    __shared__ __half Ks[32][72];
    __shared__ __half Vs[64][40];
    __shared__ __half Ps[64][40];

    const int tid  = threadIdx.x;
    const int lane = tid & 31;
    const int warp = tid >> 5;
    const int lr   = lane >> 2;
    const int lc   = lane & 3;

    const int bh = blockIdx.y;
    const int r0 = blockIdx.x * 64;
    const int b  = bh >> 4;
    const int h  = bh & 15;

    const __half* qg = g_q16 + (size_t)bh * Nn_ * HD;    // [n][d]
    const __half* kg = g_k16 + (size_t)bh * Nn_ * HD;    // [n][d]
    const __half* vg = g_v16 + (size_t)bh * HD * Nn_;    // [d][n]

    const int l15   = lane & 15;
    const int lcoff = (lane >> 4) * 8;
    const int brow  = (lane & 7) + ((lane >> 4) << 3);
    const int bcoff = ((lane >> 3) & 1) * 8;

#pragma unroll
    for (int i = 0; i < 4; i++) {
        int idx4 = i * 128 + tid;
        int row  = idx4 >> 3;
        int c8   = (idx4 & 7) * 8;
        *(uint4*)&Qs[row][c8] = *(const uint4*)(qg + (size_t)(r0 + row) * HD + c8);
    }

    float oacc[8][4];
#pragma unroll
    for (int bn = 0; bn < 8; bn++)
#pragma unroll
        for (int r = 0; r < 4; r++) oacc[bn][r] = 0.0f;
    float m0 = -3.0e38f, m1 = -3.0e38f, l0 = 0.0f, l1 = 0.0f;

    const int wrow = warp * 16;

    __syncthreads();

    for (int kt = 0; kt < Nn_ / 32; kt++) {
        const int c0 = kt * 32;

#pragma unroll
        for (int i = 0; i < 2; i++) {
            int idx4 = i * 128 + tid;
            int row  = idx4 >> 3;
            int c8   = (idx4 & 7) * 8;
            *(uint4*)&Ks[row][c8] =
                *(const uint4*)(kg + (size_t)(c0 + row) * HD + c8);
        }
#pragma unroll
        for (int i = 0; i < 2; i++) {
            int idx4 = i * 128 + tid;
            int d    = idx4 >> 2;
            int s8   = (idx4 & 3) * 8;
            *(uint4*)&Vs[d][s8] =
                *(const uint4*)(vg + (size_t)d * Nn_ + c0 + s8);
        }
        __syncthreads();

        float sacc[4][4];
#pragma unroll
        for (int bn = 0; bn < 4; bn++)
#pragma unroll
            for (int r = 0; r < 4; r++) sacc[bn][r] = 0.0f;

#pragma unroll
        for (int kk = 0; kk < 64; kk += 16) {
            uint32_t a0, a1, a2, a3;
            ldsm_x4(a0, a1, a2, a3, s2u(&Qs[wrow + l15][kk + lcoff]));
            uint32_t k0r, k1r, k2r, k3r;
            ldsm_x4(k0r, k1r, k2r, k3r, s2u(&Ks[brow][kk + bcoff]));
            mma_f16(sacc[0], a0, a1, a2, a3, k0r, k1r);
            mma_f16(sacc[1], a0, a1, a2, a3, k2r, k3r);
            ldsm_x4(k0r, k1r, k2r, k3r, s2u(&Ks[16 + brow][kk + bcoff]));
            mma_f16(sacc[2], a0, a1, a2, a3, k0r, k1r);
            mma_f16(sacc[3], a0, a1, a2, a3, k2r, k3r);
        }

        float rmax0 = -3.0e38f, rmax1 = -3.0e38f;
#pragma unroll
        for (int bn = 0; bn < 4; bn++) {
            rmax0 = fmaxf(rmax0, fmaxf(sacc[bn][0], sacc[bn][1]));
            rmax1 = fmaxf(rmax1, fmaxf(sacc[bn][2], sacc[bn][3]));
        }
        rmax0 = fmaxf(rmax0, __shfl_xor_sync(0xffffffffu, rmax0, 1));
        rmax0 = fmaxf(rmax0, __shfl_xor_sync(0xffffffffu, rmax0, 2));
        rmax1 = fmaxf(rmax1, __shfl_xor_sync(0xffffffffu, rmax1, 1));
        rmax1 = fmaxf(rmax1, __shfl_xor_sync(0xffffffffu, rmax1, 2));

        const float newm0 = fmaxf(m0, rmax0);
        const float newm1 = fmaxf(m1, rmax1);
        const float fac0  = __expf(m0 - newm0);
        const float fac1  = __expf(m1 - newm1);

        float p[4][4];
        float rsum0 = 0.0f, rsum1 = 0.0f;
#pragma unroll
        for (int bn = 0; bn < 4; bn++) {
            p[bn][0] = __expf(sacc[bn][0] - newm0);
            p[bn][1] = __expf(sacc[bn][1] - newm0);
            p[bn][2] = __expf(sacc[bn][2] - newm1);
            p[bn][3] = __expf(sacc[bn][3] - newm1);
            rsum0 += p[bn][0] + p[bn][1];
            rsum1 += p[bn][2] + p[bn][3];
        }
        rsum0 += __shfl_xor_sync(0xffffffffu, rsum0, 1);
        rsum0 += __shfl_xor_sync(0xffffffffu, rsum0, 2);
        rsum1 += __shfl_xor_sync(0xffffffffu, rsum1, 1);
        rsum1 += __shfl_xor_sync(0xffffffffu, rsum1, 2);

        l0 = l0 * fac0 + rsum0;  m0 = newm0;
        l1 = l1 * fac1 + rsum1;  m1 = newm1;
#pragma unroll
        for (int bn = 0; bn < 8; bn++) {
            oacc[bn][0] *= fac0; oacc[bn][1] *= fac0;
            oacc[bn][2] *= fac1; oacc[bn][3] *= fac1;
        }

#pragma unroll
        for (int bn = 0; bn < 4; bn++) {
            *(uint32_t*)&Ps[wrow + lr][bn * 8 + 2 * lc]     = pkh(p[bn][0], p[bn][1]);
            *(uint32_t*)&Ps[wrow + 8 + lr][bn * 8 + 2 * lc] = pkh(p[bn][2], p[bn][3]);
        }
        __syncwarp();

#pragma unroll
        for (int kk = 0; kk < 32; kk += 16) {
            uint32_t a0, a1, a2, a3;
            ldsm_x4(a0, a1, a2, a3, s2u(&Ps[wrow + l15][kk + lcoff]));
#pragma unroll
            for (int g = 0; g < 4; g++) {
                uint32_t v0, v1, v2, v3;
                ldsm_x4(v0, v1, v2, v3, s2u(&Vs[g * 16 + brow][kk + bcoff]));
                mma_f16(oacc[2 * g],     a0, a1, a2, a3, v0, v1);
                mma_f16(oacc[2 * g + 1], a0, a1, a2, a3, v2, v3);
            }
        }
        __syncthreads();
    }

    const float inv0 = 1.0f / l0;
    const float inv1 = 1.0f / l1;
    const int row0 = r0 + wrow + lr;
    const int row1 = row0 + 8;
#pragma unroll
    for (int bn = 0; bn < 8; bn++) {
        const int col = h * HD + bn * 8 + 2 * lc;
        *(float2*)(g_heads + ((size_t)(b * Nn_ + row0) * Dd) + col) =
            make_float2(oacc[bn][0] * inv0, oacc[bn][1] * inv0);
        *(float2*)(g_heads + ((size_t)(b * Nn_ + row1) * Dd) + col) =
            make_float2(oacc[bn][2] * inv1, oacc[bn][3] * inv1);
    }
}

// ---------------------------------------------------------------------------
extern "C" void kernel_launch(void* const* d_in, const int* in_sizes, int n_in,
                              void* d_out, int out_size)
{
    // Resolve inputs BY SIZE (all element counts are distinct):
    const float *x = 0, *W_qkv = 0, *b_qkv = 0, *W_o = 0, *b_o = 0;
    for (int i = 0; i < n_in; i++) {
        const float* p = (const float*)d_in[i];
        switch (in_sizes[i]) {
            case 8388608: x     = p; break;
            case 3145728: W_qkv = p; break;
            case 3072:    b_qkv = p; break;
            case 1048576: W_o   = p; break;
            case 1024:    b_o   = p; break;
            default: break;
        }
    }
    float* out = (float*)d_out;

    const int M = Bb * Nn_;     // 8192

    // 1) QKV projection (fp16 k16 mma, software-pipelined) + scatter epilogue
    {
        dim3 grid(3 * Dd / 128, M / 128);   // (24, 64)
        sgemm_kernel<1><<<grid, 256>>>(x, W_qkv, b_qkv, (float*)0, M, 3 * Dd, Dd);
    }

    // 2) Attention (fp16 k16 mma flash, ldmatrix fragments)
    {
        dim3 grid(Nn_ / 64, Bb * Hh);       // (16, 128)
        attn_mma_kernel<<<grid, 128>>>();
    }

    // 3) Output projection (fp16 k16 mma, software-pipelined)
    {
        dim3 grid(Dd / 128, M / 128);       // (8, 64)
        sgemm_kernel<2><<<grid, 256>>>((const float*)0, W_o, b_o, out, M, Dd, Dd);
    }
}

// round 15
// speedup vs baseline: 2.7683x; 1.0579x over previous
#include <cuda_runtime.h>
#include <cuda_fp16.h>
#include <cstdint>

#define Bb 8
#define Nn_ 1024
#define Dd 1024
#define Hh 16
#define HD 64
#define QSCALE 0.125f   // 64^-0.5, exact power of two

// Scratch (device globals: no allocations allowed)
__device__ __half g_x16[Bb * Nn_ * Dd];        // x fp16 [row][k]
__device__ __half g_wq16t[3 * Dd * Dd];        // W_qkv fp16 TRANSPOSED [n][k]
__device__ __half g_wo16t[Dd * Dd];            // W_o  fp16 TRANSPOSED [n][k]
__device__ __half g_q16[Bb * Hh * Nn_ * HD];   // Q fp16 [bh][n][d], pre-scaled
__device__ __half g_k16[Bb * Hh * Nn_ * HD];   // K fp16 [bh][n][d]
__device__ __half g_v16[Bb * Hh * Nn_ * HD];   // V fp16 [bh][d][n]  (d-major!)
__device__ __half g_heads16[Bb * Nn_ * Dd];    // heads fp16 [b][n][h*HD+d]

// ---------------------------------------------------------------------------
// helpers
// ---------------------------------------------------------------------------
__device__ __forceinline__ uint32_t pkh(float a, float b) {   // {lo=a, hi=b}
    uint32_t r;
    asm("cvt.rn.f16x2.f32 %0, %1, %2;" : "=r"(r) : "f"(b), "f"(a));
    return r;
}

__device__ __forceinline__ void mma_f16(float c[4],
                                        uint32_t a0, uint32_t a1,
                                        uint32_t a2, uint32_t a3,
                                        uint32_t b0, uint32_t b1) {
    asm volatile(
        "mma.sync.aligned.m16n8k16.row.col.f32.f16.f16.f32 "
        "{%0,%1,%2,%3}, {%4,%5,%6,%7}, {%8,%9}, {%0,%1,%2,%3};"
        : "+f"(c[0]), "+f"(c[1]), "+f"(c[2]), "+f"(c[3])
        : "r"(a0), "r"(a1), "r"(a2), "r"(a3), "r"(b0), "r"(b1));
}

__device__ __forceinline__ uint32_t s2u(const void* p) {
    return (uint32_t)__cvta_generic_to_shared(p);
}

__device__ __forceinline__ void ldsm_x4(uint32_t& r0, uint32_t& r1,
                                        uint32_t& r2, uint32_t& r3,
                                        uint32_t addr) {
    asm volatile("ldmatrix.sync.aligned.m8n8.x4.shared.b16 {%0,%1,%2,%3}, [%4];"
                 : "=r"(r0), "=r"(r1), "=r"(r2), "=r"(r3) : "r"(addr));
}

// ---------------------------------------------------------------------------
// Prologue: x -> fp16 (elementwise; 8 floats per thread)
// ---------------------------------------------------------------------------
__global__ __launch_bounds__(256)
void cvt_x_kernel(const float4* __restrict__ in)
{
    int i = blockIdx.x * blockDim.x + threadIdx.x;   // 0 .. 1M-1
    float4 v0 = in[2 * i];
    float4 v1 = in[2 * i + 1];
    ((uint4*)g_x16)[i] = make_uint4(pkh(v0.x, v0.y), pkh(v0.z, v0.w),
                                    pkh(v1.x, v1.y), pkh(v1.z, v1.w));
}

// ---------------------------------------------------------------------------
// Prologue: W [K][N] fp32 -> Wt [N][K] fp16 (tiled transpose)
// which: 1 -> g_wq16t, 2 -> g_wo16t
// ---------------------------------------------------------------------------
__global__ __launch_bounds__(256)
void wt_kernel(const float* __restrict__ W, int N, int Kdim, int which)
{
    __shared__ __half t[32][33];
    __half* Wt = (which == 1) ? g_wq16t : g_wo16t;

    const int n0 = blockIdx.x * 32;
    const int k0 = blockIdx.y * 32;
    const int tx = threadIdx.x & 31;
    const int ty = threadIdx.x >> 5;      // 0..7

#pragma unroll
    for (int i = 0; i < 32; i += 8)
        t[ty + i][tx] = __float2half_rn(W[(size_t)(k0 + ty + i) * N + n0 + tx]);
    __syncthreads();
#pragma unroll
    for (int i = 0; i < 32; i += 8)
        Wt[(size_t)(n0 + ty + i) * Kdim + k0 + tx] = t[tx][ty + i];
}

// ---------------------------------------------------------------------------
// fp16 tensor-core GEMM, software-pipelined, ALL-fp16 operands (no cvt in loop).
// Block 128x128, BK=32, 256 threads = 8 warps (2M x 4N), warp tile 64x32.
// Loader: per thread 2 x LDG.128 per array (16 halves!) + matching STS.128.
// MODE 1: A=g_x16, W=g_wq16t; QKV scatter epilogue (q scaled; V d-major)
// MODE 2: A=g_heads16, W=g_wo16t; fp32 C + bias
// ---------------------------------------------------------------------------
template <int MODE>
__global__ __launch_bounds__(256)
void sgemm_kernel(const float* __restrict__ bias,
                  float* __restrict__ C,
                  int M, int N, int K)
{
    __shared__ __half Ah[2][128][40];   // [buf][row][k]
    __shared__ __half Bh[2][128][40];   // [buf][n][k]

    const __half* __restrict__ A16 = (MODE == 1) ? g_x16    : g_heads16;
    const __half* __restrict__ Wt  = (MODE == 1) ? g_wq16t  : g_wo16t;

    const int tid  = threadIdx.x;
    const int lane = tid & 31;
    const int warp = tid >> 5;
    const int warpM = warp & 1;
    const int warpN = warp >> 1;

    const int r0 = blockIdx.y * 128;
    const int c0 = blockIdx.x * 128;

    // loaders: 2 threads per row, 16 halves (= 2 uint4 of 8 halves) each
    const int a_row = tid >> 1;
    const int a_kc  = (tid & 1) * 16;

    const __half* Aptr = A16 + (size_t)(r0 + a_row) * K + a_kc;
    const __half* Bptr = Wt + (size_t)(c0 + a_row) * K + a_kc;

    // ldmatrix lane constants
    const int l15   = lane & 15;
    const int lcoff = (lane >> 4) * 8;
    const int brow  = (lane & 7) + ((lane >> 4) << 3);
    const int bcoff = ((lane >> 3) & 1) * 8;

    float acc[4][4][4];
#pragma unroll
    for (int i = 0; i < 4; i++)
#pragma unroll
        for (int j = 0; j < 4; j++)
#pragma unroll
            for (int r = 0; r < 4; r++) acc[i][j][r] = 0.0f;

    const int lr = lane >> 2;
    const int lc = lane & 3;

    // prefetch registers: uint4 = 8 halves, need 2 per array per thread
    uint4 pa0, pa1, pb0, pb1;

#define GLOAD(k0) do {                                                      \
        pa0 = *(const uint4*)(Aptr + (k0));                                 \
        pa1 = *(const uint4*)(Aptr + (k0) + 8);                             \
        pb0 = *(const uint4*)(Bptr + (k0));                                 \
        pb1 = *(const uint4*)(Bptr + (k0) + 8);                             \
    } while (0)

#define SSTORE(buf) do {                                                    \
        *(uint4*)&Ah[buf][a_row][a_kc]     = pa0;                           \
        *(uint4*)&Ah[buf][a_row][a_kc + 8] = pa1;                           \
        *(uint4*)&Bh[buf][a_row][a_kc]     = pb0;                           \
        *(uint4*)&Bh[buf][a_row][a_kc + 8] = pb1;                           \
    } while (0)

    GLOAD(0);
    SSTORE(0);
    __syncthreads();

    const int NS = K / 32;
    int buf = 0;
    for (int stage = 0; stage < NS; stage++) {
        if (stage + 1 < NS) GLOAD((stage + 1) * 32);

#pragma unroll
        for (int kk = 0; kk < 32; kk += 16) {
            uint32_t af[4][4];
#pragma unroll
            for (int am = 0; am < 4; am++)
                ldsm_x4(af[am][0], af[am][1], af[am][2], af[am][3],
                        s2u(&Ah[buf][warpM * 64 + am * 16 + l15][kk + lcoff]));
#pragma unroll
            for (int g = 0; g < 2; g++) {
                uint32_t b0, b1, b2, b3;
                ldsm_x4(b0, b1, b2, b3,
                        s2u(&Bh[buf][warpN * 32 + g * 16 + brow][kk + bcoff]));
#pragma unroll
                for (int am = 0; am < 4; am++) {
                    mma_f16(acc[am][2 * g],     af[am][0], af[am][1], af[am][2],
                            af[am][3], b0, b1);
                    mma_f16(acc[am][2 * g + 1], af[am][0], af[am][1], af[am][2],
                            af[am][3], b2, b3);
                }
            }
        }

        if (stage + 1 < NS) SSTORE(buf ^ 1);
        __syncthreads();
        buf ^= 1;
    }
#undef GLOAD
#undef SSTORE

    // ---- epilogue ----
#pragma unroll
    for (int am = 0; am < 4; am++) {
        const int row0 = r0 + warpM * 64 + am * 16 + lr;
        const int row1 = row0 + 8;
#pragma unroll
        for (int bn = 0; bn < 4; bn++) {
            const int atomcol = c0 + warpN * 32 + bn * 8;
            const int colp = atomcol + lc * 2;
            const float b0v = bias[colp];
            const float b1v = bias[colp + 1];
            float v00 = acc[am][bn][0] + b0v, v01 = acc[am][bn][1] + b1v;
            float v10 = acc[am][bn][2] + b0v, v11 = acc[am][bn][3] + b1v;

            if (MODE == 2) {
                *(float2*)(C + (size_t)row0 * N + colp) = make_float2(v00, v01);
                *(float2*)(C + (size_t)row1 * N + colp) = make_float2(v10, v11);
            } else {
                const int h     = atomcol / 192;
                const int rem   = atomcol % 192;
                const int t     = rem / 64;          // 0=q 1=k 2=v
                const int dbase = (rem % 64) + lc * 2;
                const int b0r = row0 >> 10, n0 = row0 & 1023;
                const int b1r = row1 >> 10, n1 = row1 & 1023;

                if (t == 2) {
                    const size_t vb0 = ((size_t)(b0r * Hh + h) * HD + dbase) * Nn_;
                    const size_t vb1 = ((size_t)(b1r * Hh + h) * HD + dbase) * Nn_;
                    g_v16[vb0 + n0]       = __float2half_rn(v00);
                    g_v16[vb0 + Nn_ + n0] = __float2half_rn(v01);
                    g_v16[vb1 + n1]       = __float2half_rn(v10);
                    g_v16[vb1 + Nn_ + n1] = __float2half_rn(v11);
                } else {
                    __half* dst = (t == 0) ? g_q16 : g_k16;
                    const float sc = (t == 0) ? QSCALE : 1.0f;
                    const size_t off0 = (((size_t)(b0r * Hh + h) << 10) + n0) * HD + dbase;
                    const size_t off1 = (((size_t)(b1r * Hh + h) << 10) + n1) * HD + dbase;
                    *(uint32_t*)(dst + off0) = pkh(v00 * sc, v01 * sc);
                    *(uint32_t*)(dst + off1) = pkh(v10 * sc, v11 * sc);
                }
            }
        }
    }
}

// ---------------------------------------------------------------------------
// fp16 tensor-core flash attention (structure unchanged from R13 -- passing);
// heads written directly as fp16 (same rounding as the old O-proj loader).
// ---------------------------------------------------------------------------
__global__ __launch_bounds__(128, 4)
void attn_mma_kernel()
{
    __shared__ __half Qs[64][72];
    __shared__ __half Ks[32][72];
    __shared__ __half Vs[64][40];
    __shared__ __half Ps[64][40];

    const int tid  = threadIdx.x;
    const int lane = tid & 31;
    const int warp = tid >> 5;
    const int lr   = lane >> 2;
    const int lc   = lane & 3;

    const int bh = blockIdx.y;
    const int r0 = blockIdx.x * 64;
    const int b  = bh >> 4;
    const int h  = bh & 15;

    const __half* qg = g_q16 + (size_t)bh * Nn_ * HD;    // [n][d]
    const __half* kg = g_k16 + (size_t)bh * Nn_ * HD;    // [n][d]
    const __half* vg = g_v16 + (size_t)bh * HD * Nn_;    // [d][n]

    const int l15   = lane & 15;
    const int lcoff = (lane >> 4) * 8;
    const int brow  = (lane & 7) + ((lane >> 4) << 3);
    const int bcoff = ((lane >> 3) & 1) * 8;

#pragma unroll
    for (int i = 0; i < 4; i++) {
        int idx4 = i * 128 + tid;
        int row  = idx4 >> 3;
        int c8   = (idx4 & 7) * 8;
        *(uint4*)&Qs[row][c8] = *(const uint4*)(qg + (size_t)(r0 + row) * HD + c8);
    }

    float oacc[8][4];
#pragma unroll
    for (int bn = 0; bn < 8; bn++)
#pragma unroll
        for (int r = 0; r < 4; r++) oacc[bn][r] = 0.0f;
    float m0 = -3.0e38f, m1 = -3.0e38f, l0 = 0.0f, l1 = 0.0f;

    const int wrow = warp * 16;

    __syncthreads();

    for (int kt = 0; kt < Nn_ / 32; kt++) {
        const int c0 = kt * 32;

#pragma unroll
        for (int i = 0; i < 2; i++) {
            int idx4 = i * 128 + tid;
            int row  = idx4 >> 3;
            int c8   = (idx4 & 7) * 8;
            *(uint4*)&Ks[row][c8] =
                *(const uint4*)(kg + (size_t)(c0 + row) * HD + c8);
        }
#pragma unroll
        for (int i = 0; i < 2; i++) {
            int idx4 = i * 128 + tid;
            int d    = idx4 >> 2;
            int s8   = (idx4 & 3) * 8;
            *(uint4*)&Vs[d][s8] =
                *(const uint4*)(vg + (size_t)d * Nn_ + c0 + s8);
        }
        __syncthreads();

        float sacc[4][4];
#pragma unroll
        for (int bn = 0; bn < 4; bn++)
#pragma unroll
            for (int r = 0; r < 4; r++) sacc[bn][r] = 0.0f;

#pragma unroll
        for (int kk = 0; kk < 64; kk += 16) {
            uint32_t a0, a1, a2, a3;
            ldsm_x4(a0, a1, a2, a3, s2u(&Qs[wrow + l15][kk + lcoff]));
            uint32_t k0r, k1r, k2r, k3r;
            ldsm_x4(k0r, k1r, k2r, k3r, s2u(&Ks[brow][kk + bcoff]));
            mma_f16(sacc[0], a0, a1, a2, a3, k0r, k1r);
            mma_f16(sacc[1], a0, a1, a2, a3, k2r, k3r);
            ldsm_x4(k0r, k1r, k2r, k3r, s2u(&Ks[16 + brow][kk + bcoff]));
            mma_f16(sacc[2], a0, a1, a2, a3, k0r, k1r);
            mma_f16(sacc[3], a0, a1, a2, a3, k2r, k3r);
        }

        float rmax0 = -3.0e38f, rmax1 = -3.0e38f;
#pragma unroll
        for (int bn = 0; bn < 4; bn++) {
            rmax0 = fmaxf(rmax0, fmaxf(sacc[bn][0], sacc[bn][1]));
            rmax1 = fmaxf(rmax1, fmaxf(sacc[bn][2], sacc[bn][3]));
        }
        rmax0 = fmaxf(rmax0, __shfl_xor_sync(0xffffffffu, rmax0, 1));
        rmax0 = fmaxf(rmax0, __shfl_xor_sync(0xffffffffu, rmax0, 2));
        rmax1 = fmaxf(rmax1, __shfl_xor_sync(0xffffffffu, rmax1, 1));
        rmax1 = fmaxf(rmax1, __shfl_xor_sync(0xffffffffu, rmax1, 2));

        const float newm0 = fmaxf(m0, rmax0);
        const float newm1 = fmaxf(m1, rmax1);
        const float fac0  = __expf(m0 - newm0);
        const float fac1  = __expf(m1 - newm1);

        float p[4][4];
        float rsum0 = 0.0f, rsum1 = 0.0f;
#pragma unroll
        for (int bn = 0; bn < 4; bn++) {
            p[bn][0] = __expf(sacc[bn][0] - newm0);
            p[bn][1] = __expf(sacc[bn][1] - newm0);
            p[bn][2] = __expf(sacc[bn][2] - newm1);
            p[bn][3] = __expf(sacc[bn][3] - newm1);
            rsum0 += p[bn][0] + p[bn][1];
            rsum1 += p[bn][2] + p[bn][3];
        }
        rsum0 += __shfl_xor_sync(0xffffffffu, rsum0, 1);
        rsum0 += __shfl_xor_sync(0xffffffffu, rsum0, 2);
        rsum1 += __shfl_xor_sync(0xffffffffu, rsum1, 1);
        rsum1 += __shfl_xor_sync(0xffffffffu, rsum1, 2);

        l0 = l0 * fac0 + rsum0;  m0 = newm0;
        l1 = l1 * fac1 + rsum1;  m1 = newm1;
#pragma unroll
        for (int bn = 0; bn < 8; bn++) {
            oacc[bn][0] *= fac0; oacc[bn][1] *= fac0;
            oacc[bn][2] *= fac1; oacc[bn][3] *= fac1;
        }

#pragma unroll
        for (int bn = 0; bn < 4; bn++) {
            *(uint32_t*)&Ps[wrow + lr][bn * 8 + 2 * lc]     = pkh(p[bn][0], p[bn][1]);
            *(uint32_t*)&Ps[wrow + 8 + lr][bn * 8 + 2 * lc] = pkh(p[bn][2], p[bn][3]);
        }
        __syncwarp();

#pragma unroll
        for (int kk = 0; kk < 32; kk += 16) {
            uint32_t a0, a1, a2, a3;
            ldsm_x4(a0, a1, a2, a3, s2u(&Ps[wrow + l15][kk + lcoff]));
#pragma unroll
            for (int g = 0; g < 4; g++) {
                uint32_t v0, v1, v2, v3;
                ldsm_x4(v0, v1, v2, v3, s2u(&Vs[g * 16 + brow][kk + bcoff]));
                mma_f16(oacc[2 * g],     a0, a1, a2, a3, v0, v1);
                mma_f16(oacc[2 * g + 1], a0, a1, a2, a3, v2, v3);
            }
        }
        __syncthreads();
    }

    const float inv0 = 1.0f / l0;
    const float inv1 = 1.0f / l1;
    const int row0 = r0 + wrow + lr;
    const int row1 = row0 + 8;
#pragma unroll
    for (int bn = 0; bn < 8; bn++) {
        const int col = h * HD + bn * 8 + 2 * lc;
        *(uint32_t*)(g_heads16 + ((size_t)(b * Nn_ + row0) * Dd) + col) =
            pkh(oacc[bn][0] * inv0, oacc[bn][1] * inv0);
        *(uint32_t*)(g_heads16 + ((size_t)(b * Nn_ + row1) * Dd) + col) =
            pkh(oacc[bn][2] * inv1, oacc[bn][3] * inv1);
    }
}

// ---------------------------------------------------------------------------
extern "C" void kernel_launch(void* const* d_in, const int* in_sizes, int n_in,
                              void* d_out, int out_size)
{
    // Resolve inputs BY SIZE (all element counts are distinct):
    const float *x = 0, *W_qkv = 0, *b_qkv = 0, *W_o = 0, *b_o = 0;
    for (int i = 0; i < n_in; i++) {
        const float* p = (const float*)d_in[i];
        switch (in_sizes[i]) {
            case 8388608: x     = p; break;
            case 3145728: W_qkv = p; break;
            case 3072:    b_qkv = p; break;
            case 1048576: W_o   = p; break;
            case 1024:    b_o   = p; break;
            default: break;
        }
    }
    float* out = (float*)d_out;

    const int M = Bb * Nn_;     // 8192

    // 0) prologue: one-time fp16 conversion (x) and fp16+transpose (weights)
    cvt_x_kernel<<<8388608 / 8 / 256, 256>>>((const float4*)x);
    {
        dim3 g1(3 * Dd / 32, Dd / 32);      // (96, 32)
        wt_kernel<<<g1, 256>>>(W_qkv, 3 * Dd, Dd, 1);
        dim3 g2(Dd / 32, Dd / 32);          // (32, 32)
        wt_kernel<<<g2, 256>>>(W_o, Dd, Dd, 2);
    }

    // 1) QKV projection (fp16 mma, pipelined, all-fp16 operands) + scatter
    {
        dim3 grid(3 * Dd / 128, M / 128);   // (24, 64)
        sgemm_kernel<1><<<grid, 256>>>(b_qkv, (float*)0, M, 3 * Dd, Dd);
    }

    // 2) Attention (fp16 mma flash)
    {
        dim3 grid(Nn_ / 64, Bb * Hh);       // (16, 128)
        attn_mma_kernel<<<grid, 128>>>();
    }

    // 3) Output projection
    {
        dim3 grid(Dd / 128, M / 128);       // (8, 64)
        sgemm_kernel<2><<<grid, 256>>>(b_o, out, M, Dd, Dd);
    }
}